// round 13
// baseline (speedup 1.0000x reference)
#include <cuda_runtime.h>
#include <cuda_bf16.h>
#include <math.h>

#define Sdim 196
#define Bn   64
#define Cdim 1024
#define Hdim 1024
#define Edim 512
#define Vdim 32000
#define NSTEP 19
#define NVBLK (Vdim / 256)   // 125 logits blocks

// ---------------- scratch (device globals) -----------------------------------
__device__ __nv_bfloat16 g_ctxp_bf16[(size_t)Sdim * Bn * Cdim];
__device__ __nv_bfloat16 g_ctx_bf16[(size_t)Sdim * Bn * Cdim];
__device__ __nv_bfloat16 g_WctxT_bf16[Cdim * Cdim];
__device__ __nv_bfloat16 g_WhidT_bf16[Hdim * Cdim];
__device__ __nv_bfloat16 g_Wih_bf16[3 * Hdim * (Edim + Cdim)];
__device__ __nv_bfloat16 g_Whh_bf16[3 * Hdim * Hdim];
__device__ __nv_bfloat16 g_h2o_bf16[Edim * Hdim];
__device__ __nv_bfloat16 g_octx_bf16[Edim * Cdim];
__device__ __nv_bfloat16 g_Wo2p_bf16[(size_t)Vdim * Edim];
__device__ __nv_bfloat16 g_p_bf16[Bn * Edim];
__device__ float g_h[Bn * Hdim];
__device__ float g_hq_part[4 * Bn * Cdim];
__device__ float g_z[Bn * Cdim];
__device__ float g_gi_part[4 * Bn * 3 * Hdim];
__device__ float g_gh_part[4 * Bn * 3 * Hdim];
__device__ float g_pm[NVBLK * Bn];
__device__ float g_ps[NVBLK * Bn];
__device__ float g_ltgt[Bn];
__device__ float g_nll[NSTEP * Bn];

// ---------------- fast math ---------------------------------------------------
__device__ __forceinline__ float ftanh(float x) {
    float xc = fminf(fmaxf(x, -15.f), 15.f);
    float e = __expf(2.f * xc);
    return __fdividef(e - 1.f, e + 1.f);
}
__device__ __forceinline__ float ftanh_fast(float x) {
    float y;
    asm("tanh.approx.f32 %0, %1;" : "=f"(y) : "f"(x));
    return y;
}
__device__ __forceinline__ float fsig(float x) {
    return __fdividef(1.f, 1.f + __expf(-x));
}
__device__ __forceinline__ void mma_bf16(float* d, const unsigned* a4, const unsigned* b2) {
    asm volatile(
        "mma.sync.aligned.m16n8k16.row.col.f32.bf16.bf16.f32 "
        "{%0,%1,%2,%3}, {%4,%5,%6,%7}, {%8,%9}, {%0,%1,%2,%3};\n"
        : "+f"(d[0]), "+f"(d[1]), "+f"(d[2]), "+f"(d[3])
        : "r"(a4[0]), "r"(a4[1]), "r"(a4[2]), "r"(a4[3]), "r"(b2[0]), "r"(b2[1]));
}
__device__ __forceinline__ void lse_upd(float& m, float& s, float v) {
    if (v > m) { s = s * __expf(m - v) + 1.f; m = v; }
    else       { s += __expf(v - m); }
}
__device__ __forceinline__ void lse_comb(float& m, float& s, float m2, float s2) {
    float M = fmaxf(m, m2);
    s = s * __expf(m - M) + s2 * __expf(m2 - M);
    m = M;
}

// ---------------- block reductions (fixed order) ------------------------------
__device__ __forceinline__ float blockReduceSum(float v, float* red) {
    #pragma unroll
    for (int o = 16; o; o >>= 1) v += __shfl_xor_sync(0xffffffffu, v, o);
    if ((threadIdx.x & 31) == 0) red[threadIdx.x >> 5] = v;
    __syncthreads();
    float t = 0.f;
    int nw = blockDim.x >> 5;
    for (int i = 0; i < nw; i++) t += red[i];
    __syncthreads();
    return t;
}
__device__ __forceinline__ float blockReduceMax(float v, float* red) {
    #pragma unroll
    for (int o = 16; o; o >>= 1) v = fmaxf(v, __shfl_xor_sync(0xffffffffu, v, o));
    if ((threadIdx.x & 31) == 0) red[threadIdx.x >> 5] = v;
    __syncthreads();
    float t = red[0];
    int nw = blockDim.x >> 5;
    for (int i = 1; i < nw; i++) t = fmaxf(t, red[i]);
    __syncthreads();
    return t;
}

// ---------------- one-time prep kernels ---------------------------------------
__global__ void k_transpose_bf16(const float* __restrict__ in, __nv_bfloat16* __restrict__ out, int R, int Ccols) {
    __shared__ float t[32][33];
    int c0 = blockIdx.x * 32, r0 = blockIdx.y * 32;
    #pragma unroll
    for (int i = 0; i < 4; i++)
        t[threadIdx.y + i * 8][threadIdx.x] = in[(size_t)(r0 + threadIdx.y + i * 8) * Ccols + c0 + threadIdx.x];
    __syncthreads();
    #pragma unroll
    for (int i = 0; i < 4; i++)
        out[(size_t)(c0 + threadIdx.y + i * 8) * R + r0 + threadIdx.x] =
            __float2bfloat16_rn(t[threadIdx.x][threadIdx.y + i * 8]);
}

// all plain fp32->bf16 conversions in one launch (segmented by float4 index)
#define CVT_N0 ((size_t)Sdim * Bn * Cdim / 4)
#define CVT_N1 (CVT_N0 + (size_t)3 * Hdim * (Edim + Cdim) / 4)
#define CVT_N2 (CVT_N1 + (size_t)3 * Hdim * Hdim / 4)
#define CVT_N3 (CVT_N2 + (size_t)Edim * Hdim / 4)
#define CVT_N4 (CVT_N3 + (size_t)Edim * Cdim / 4)
#define CVT_N5 (CVT_N4 + (size_t)Vdim * Edim / 4)
__global__ void k_cvt_all(const float* __restrict__ ctx, const float* __restrict__ Wih,
                          const float* __restrict__ Whh, const float* __restrict__ h2o,
                          const float* __restrict__ octx, const float* __restrict__ o2p) {
    size_t i = (size_t)blockIdx.x * 256 + threadIdx.x;   // float4 index
    const float* src; __nv_bfloat16* dst; size_t off;
    if      (i < CVT_N0) { src = ctx;  dst = g_ctx_bf16;  off = i; }
    else if (i < CVT_N1) { src = Wih;  dst = g_Wih_bf16;  off = i - CVT_N0; }
    else if (i < CVT_N2) { src = Whh;  dst = g_Whh_bf16;  off = i - CVT_N1; }
    else if (i < CVT_N3) { src = h2o;  dst = g_h2o_bf16;  off = i - CVT_N2; }
    else if (i < CVT_N4) { src = octx; dst = g_octx_bf16; off = i - CVT_N3; }
    else if (i < CVT_N5) { src = o2p;  dst = g_Wo2p_bf16; off = i - CVT_N4; }
    else return;
    float4 v = *(const float4*)&src[off * 4];
    __nv_bfloat162* o = (__nv_bfloat162*)&dst[off * 4];
    o[0] = __floats2bfloat162_rn(v.x, v.y);
    o[1] = __floats2bfloat162_rn(v.z, v.w);
}

// zero h and hq_part: h0 = 0 => hq0 = 0
__global__ void k_zero_init() {
    int i = blockIdx.x * 256 + threadIdx.x;
    if (i < Bn * Hdim) g_h[i] = 0.f;
    else g_hq_part[i - Bn * Hdim] = 0.f;
}

// ============ BF16 NT GEMM, 128x128 tile, bf16 out (ctx_proj) =================
__global__ __launch_bounds__(256) void gemm_bf16_m128(
    const __nv_bfloat16* __restrict__ A, const __nv_bfloat16* __restrict__ B,
    __nv_bfloat16* __restrict__ C, int N, int K) {
    __shared__ __nv_bfloat16 As[128][72];
    __shared__ __nv_bfloat16 Bs[128][72];
    const int row0 = blockIdx.y * 128, col0 = blockIdx.x * 128;
    const int tid = threadIdx.x;
    const int wid = tid >> 5, lane = tid & 31;
    const int gID = lane >> 2, tig = lane & 3;
    const int m0w = (wid >> 2) * 64, n0w = (wid & 3) * 32;
    const int lrow = tid >> 1, lcol = (tid & 1) * 32;
    float acc[4][4][4] = {};
    for (int k0 = 0; k0 < K; k0 += 64) {
        #pragma unroll
        for (int i = 0; i < 4; i++) {
            *(uint4*)&As[lrow][lcol + i * 8] = *(const uint4*)&A[(size_t)(row0 + lrow) * K + k0 + lcol + i * 8];
            *(uint4*)&Bs[lrow][lcol + i * 8] = *(const uint4*)&B[(size_t)(col0 + lrow) * K + k0 + lcol + i * 8];
        }
        __syncthreads();
        #pragma unroll
        for (int kk = 0; kk < 4; kk++) {
            const int kb = kk * 16;
            unsigned af[4][4], bf[4][2];
            #pragma unroll
            for (int mi = 0; mi < 4; mi++) {
                int r = m0w + mi * 16 + gID;
                int c = kb + tig * 2;
                af[mi][0] = *(const unsigned*)&As[r][c];
                af[mi][1] = *(const unsigned*)&As[r + 8][c];
                af[mi][2] = *(const unsigned*)&As[r][c + 8];
                af[mi][3] = *(const unsigned*)&As[r + 8][c + 8];
            }
            #pragma unroll
            for (int ni = 0; ni < 4; ni++) {
                int n = n0w + ni * 8 + gID;
                int c = kb + tig * 2;
                bf[ni][0] = *(const unsigned*)&Bs[n][c];
                bf[ni][1] = *(const unsigned*)&Bs[n][c + 8];
            }
            #pragma unroll
            for (int mi = 0; mi < 4; mi++)
                #pragma unroll
                for (int ni = 0; ni < 4; ni++)
                    mma_bf16(acc[mi][ni], af[mi], bf[ni]);
        }
        __syncthreads();
    }
    #pragma unroll
    for (int mi = 0; mi < 4; mi++)
        #pragma unroll
        for (int ni = 0; ni < 4; ni++) {
            int r = row0 + m0w + mi * 16 + gID;
            int c = col0 + n0w + ni * 8 + tig * 2;
            *(__nv_bfloat162*)&C[(size_t)r * N + c]       = __floats2bfloat162_rn(acc[mi][ni][0], acc[mi][ni][1]);
            *(__nv_bfloat162*)&C[(size_t)(r + 8) * N + c] = __floats2bfloat162_rn(acc[mi][ni][2], acc[mi][ni][3]);
        }
}

// ============ combined launch: hq (split-K4) + fused o1o2->p ==================
// blockIdx.y == 0: hq = h @ WhidT^T, N=Cdim, split-K over blockIdx.z
// blockIdx.y == 1: full-K dual GEMM o1 = h@h2o^T, o2 = z@octx^T (N=Edim,
//                  blockIdx.z==0 only) with p = tanh(tanh(o1+b1)+emb+o2+b2).
// Shared memory: one 36864B buffer aliased by both branches (mutually exclusive).
__global__ __launch_bounds__(256) void gemm_bf16_hq_o1o2p(
    const float* __restrict__ h, const int* __restrict__ y, int t,
    const float* __restrict__ embW,
    const __nv_bfloat16* __restrict__ Bh2o, const __nv_bfloat16* __restrict__ Boctx,
    const __nv_bfloat16* __restrict__ Bhid,
    const float* __restrict__ h2o_b, const float* __restrict__ octx_b,
    float* __restrict__ Chq) {
    __shared__ __align__(16) unsigned char sbuf[4 * 9216];
    const int tid = threadIdx.x;
    const int wid = tid >> 5, lane = tid & 31;
    const int gID = lane >> 2, tig = lane & 3;
    const int lrow = tid >> 2, lseg = (tid & 3) * 16;

    if (blockIdx.y == 0) {
        // ---- hq split-K ----
        __nv_bfloat16 (*As)[72] = reinterpret_cast<__nv_bfloat16(*)[72]>(sbuf);
        __nv_bfloat16 (*Bs)[72] = reinterpret_cast<__nv_bfloat16(*)[72]>(sbuf + 9216);
        const int col0 = blockIdx.x * 64;
        const int K = Hdim, kChunk = Hdim / 4;
        const int kbase = blockIdx.z * kChunk;
        float acc[4][4] = {};
        for (int kt = 0; kt < kChunk; kt += 64) {
            const int k0 = kbase + kt;
            #pragma unroll
            for (int i = 0; i < 4; i++) {
                float4 a = *(const float4*)&h[(size_t)lrow * K + k0 + lseg + i * 4];
                __nv_bfloat162* d = (__nv_bfloat162*)&As[lrow][lseg + i * 4];
                d[0] = __floats2bfloat162_rn(a.x, a.y);
                d[1] = __floats2bfloat162_rn(a.z, a.w);
            }
            *(uint4*)&Bs[lrow][lseg]     = *(const uint4*)&Bhid[(size_t)(col0 + lrow) * K + k0 + lseg];
            *(uint4*)&Bs[lrow][lseg + 8] = *(const uint4*)&Bhid[(size_t)(col0 + lrow) * K + k0 + lseg + 8];
            __syncthreads();
            #pragma unroll
            for (int kk = 0; kk < 4; kk++) {
                const int c = kk * 16 + tig * 2;
                const int n = wid * 8 + gID;
                unsigned bfv[2];
                bfv[0] = *(const unsigned*)&Bs[n][c];
                bfv[1] = *(const unsigned*)&Bs[n][c + 8];
                #pragma unroll
                for (int mi = 0; mi < 4; mi++) {
                    int r = mi * 16 + gID;
                    unsigned af[4];
                    af[0] = *(const unsigned*)&As[r][c];
                    af[1] = *(const unsigned*)&As[r + 8][c];
                    af[2] = *(const unsigned*)&As[r][c + 8];
                    af[3] = *(const unsigned*)&As[r + 8][c + 8];
                    mma_bf16(acc[mi], af, bfv);
                }
            }
            __syncthreads();
        }
        float* Cp = Chq + (size_t)blockIdx.z * 64 * Cdim;
        #pragma unroll
        for (int mi = 0; mi < 4; mi++) {
            int r = mi * 16 + gID;
            int c = col0 + wid * 8 + tig * 2;
            *(float2*)&Cp[(size_t)r * Cdim + c]       = make_float2(acc[mi][0], acc[mi][1]);
            *(float2*)&Cp[(size_t)(r + 8) * Cdim + c] = make_float2(acc[mi][2], acc[mi][3]);
        }
    } else {
        // ---- fused o1/o2 -> p ----
        if (blockIdx.z != 0 || blockIdx.x >= Edim / 64) return;
        __nv_bfloat16 (*As1)[72] = reinterpret_cast<__nv_bfloat16(*)[72]>(sbuf);
        __nv_bfloat16 (*Bs1)[72] = reinterpret_cast<__nv_bfloat16(*)[72]>(sbuf + 9216);
        __nv_bfloat16 (*As2)[72] = reinterpret_cast<__nv_bfloat16(*)[72]>(sbuf + 2 * 9216);
        __nv_bfloat16 (*Bs2)[72] = reinterpret_cast<__nv_bfloat16(*)[72]>(sbuf + 3 * 9216);
        const int col0 = blockIdx.x * 64;
        const int K = Hdim;
        float acc1[4][4] = {}, acc2[4][4] = {};
        for (int k0 = 0; k0 < K; k0 += 64) {
            #pragma unroll
            for (int i = 0; i < 4; i++) {
                float4 a = *(const float4*)&h[(size_t)lrow * K + k0 + lseg + i * 4];
                __nv_bfloat162* d = (__nv_bfloat162*)&As1[lrow][lseg + i * 4];
                d[0] = __floats2bfloat162_rn(a.x, a.y);
                d[1] = __floats2bfloat162_rn(a.z, a.w);
                float4 zz = *(const float4*)&g_z[(size_t)lrow * Cdim + k0 + lseg + i * 4];
                __nv_bfloat162* d2 = (__nv_bfloat162*)&As2[lrow][lseg + i * 4];
                d2[0] = __floats2bfloat162_rn(zz.x, zz.y);
                d2[1] = __floats2bfloat162_rn(zz.z, zz.w);
            }
            *(uint4*)&Bs1[lrow][lseg]     = *(const uint4*)&Bh2o[(size_t)(col0 + lrow) * K + k0 + lseg];
            *(uint4*)&Bs1[lrow][lseg + 8] = *(const uint4*)&Bh2o[(size_t)(col0 + lrow) * K + k0 + lseg + 8];
            *(uint4*)&Bs2[lrow][lseg]     = *(const uint4*)&Boctx[(size_t)(col0 + lrow) * Cdim + k0 + lseg];
            *(uint4*)&Bs2[lrow][lseg + 8] = *(const uint4*)&Boctx[(size_t)(col0 + lrow) * Cdim + k0 + lseg + 8];
            __syncthreads();
            #pragma unroll
            for (int kk = 0; kk < 4; kk++) {
                const int c = kk * 16 + tig * 2;
                const int n = wid * 8 + gID;
                unsigned b1[2], b2[2];
                b1[0] = *(const unsigned*)&Bs1[n][c];
                b1[1] = *(const unsigned*)&Bs1[n][c + 8];
                b2[0] = *(const unsigned*)&Bs2[n][c];
                b2[1] = *(const unsigned*)&Bs2[n][c + 8];
                #pragma unroll
                for (int mi = 0; mi < 4; mi++) {
                    int r = mi * 16 + gID;
                    unsigned a1[4], a2[4];
                    a1[0] = *(const unsigned*)&As1[r][c];
                    a1[1] = *(const unsigned*)&As1[r + 8][c];
                    a1[2] = *(const unsigned*)&As1[r][c + 8];
                    a1[3] = *(const unsigned*)&As1[r + 8][c + 8];
                    a2[0] = *(const unsigned*)&As2[r][c];
                    a2[1] = *(const unsigned*)&As2[r + 8][c];
                    a2[2] = *(const unsigned*)&As2[r][c + 8];
                    a2[3] = *(const unsigned*)&As2[r + 8][c + 8];
                    mma_bf16(acc1[mi], a1, b1);
                    mma_bf16(acc2[mi], a2, b2);
                }
            }
            __syncthreads();
        }
        // epilogue: p = tanh( tanh(o1 + b1) + emb + o2 + b2 )
        #pragma unroll
        for (int mi = 0; mi < 4; mi++) {
            int r = mi * 16 + gID, r2 = r + 8;
            int c = col0 + wid * 8 + tig * 2;
            float b1a = h2o_b[c], b1b = h2o_b[c + 1];
            float b2a = octx_b[c], b2b = octx_b[c + 1];
            const float* er  = &embW[(size_t)y[t * Bn + r]  * Edim];
            const float* er2 = &embW[(size_t)y[t * Bn + r2] * Edim];
            float p0 = ftanh(ftanh(acc1[mi][0] + b1a) + er[c]     + acc2[mi][0] + b2a);
            float p1 = ftanh(ftanh(acc1[mi][1] + b1b) + er[c + 1] + acc2[mi][1] + b2b);
            float p2 = ftanh(ftanh(acc1[mi][2] + b1a) + er2[c]    + acc2[mi][2] + b2a);
            float p3 = ftanh(ftanh(acc1[mi][3] + b1b) + er2[c + 1]+ acc2[mi][3] + b2b);
            *(__nv_bfloat162*)&g_p_bf16[r  * Edim + c] = __floats2bfloat162_rn(p0, p1);
            *(__nv_bfloat162*)&g_p_bf16[r2 * Edim + c] = __floats2bfloat162_rn(p2, p3);
        }
    }
}

// ============ merged GRU GEMMs (bf16): y=0 -> gi (A gathered), y=1 -> gh ======
__global__ __launch_bounds__(256) void gemm_bf16_gigh_sk(
    const float* __restrict__ embW, const int* __restrict__ y, int t,
    const __nv_bfloat16* __restrict__ Wih, float* __restrict__ Cgi,
    const __nv_bfloat16* __restrict__ Whh, float* __restrict__ Cgh) {
    const bool is_gi = (blockIdx.y == 0);
    const int K      = is_gi ? (Edim + Cdim) : Hdim;
    const int kChunk = is_gi ? ((Edim + Cdim) / 4) : (Hdim / 4);
    const __nv_bfloat16* B = is_gi ? Wih : Whh;
    float* C = is_gi ? Cgi : Cgh;
    const int N = 3 * Hdim;
    __shared__ __nv_bfloat16 As[64][72];
    __shared__ __nv_bfloat16 Bs[64][72];
    const int col0 = blockIdx.x * 64;
    const int kbase = blockIdx.z * kChunk;
    const int tid = threadIdx.x;
    const int wid = tid >> 5, lane = tid & 31;
    const int gID = lane >> 2, tig = lane & 3;
    const int lrow = tid >> 2, lseg = (tid & 3) * 16;
    const int yid = is_gi ? y[t * Bn + lrow] : 0;
    float acc[4][4] = {};
    for (int kt = 0; kt < kChunk; kt += 64) {
        const int k0 = kbase + kt;
        const float* Arow;
        if (is_gi) Arow = (k0 < Edim) ? &embW[(size_t)yid * Edim + k0]
                                      : &g_z[lrow * Cdim + (k0 - Edim)];
        else       Arow = &g_h[lrow * Hdim + k0];
        #pragma unroll
        for (int i = 0; i < 4; i++) {
            float4 a = *(const float4*)&Arow[lseg + i * 4];
            __nv_bfloat162* d = (__nv_bfloat162*)&As[lrow][lseg + i * 4];
            d[0] = __floats2bfloat162_rn(a.x, a.y);
            d[1] = __floats2bfloat162_rn(a.z, a.w);
        }
        *(uint4*)&Bs[lrow][lseg]     = *(const uint4*)&B[(size_t)(col0 + lrow) * K + k0 + lseg];
        *(uint4*)&Bs[lrow][lseg + 8] = *(const uint4*)&B[(size_t)(col0 + lrow) * K + k0 + lseg + 8];
        __syncthreads();
        #pragma unroll
        for (int kk = 0; kk < 4; kk++) {
            const int c = kk * 16 + tig * 2;
            const int n = wid * 8 + gID;
            unsigned bfv[2];
            bfv[0] = *(const unsigned*)&Bs[n][c];
            bfv[1] = *(const unsigned*)&Bs[n][c + 8];
            #pragma unroll
            for (int mi = 0; mi < 4; mi++) {
                int r = mi * 16 + gID;
                unsigned af[4];
                af[0] = *(const unsigned*)&As[r][c];
                af[1] = *(const unsigned*)&As[r + 8][c];
                af[2] = *(const unsigned*)&As[r][c + 8];
                af[3] = *(const unsigned*)&As[r + 8][c + 8];
                mma_bf16(acc[mi], af, bfv);
            }
        }
        __syncthreads();
    }
    float* Cp = C + (size_t)blockIdx.z * 64 * N;
    #pragma unroll
    for (int mi = 0; mi < 4; mi++) {
        int r = mi * 16 + gID;
        int c = col0 + wid * 8 + tig * 2;
        *(float2*)&Cp[(size_t)r * N + c]       = make_float2(acc[mi][0], acc[mi][1]);
        *(float2*)&Cp[(size_t)(r + 8) * N + c] = make_float2(acc[mi][2], acc[mi][3]);
    }
}

// ============ BF16 logits GEMM + fused partial NLL ============================
__global__ __launch_bounds__(256) void gemm_bf16_logits_nll(
    const __nv_bfloat16* __restrict__ A, const __nv_bfloat16* __restrict__ B,
    const float* __restrict__ bias, const int* __restrict__ y, int t, int K) {
    __shared__ __align__(16) unsigned char sbuf[9216 + 36864];
    __nv_bfloat16 (*As)[72] = reinterpret_cast<__nv_bfloat16(*)[72]>(sbuf);
    __nv_bfloat16 (*Bs)[72] = reinterpret_cast<__nv_bfloat16(*)[72]>(sbuf + 9216);
    float (*sm)[8] = reinterpret_cast<float(*)[8]>(sbuf);           // overlays As
    float (*ss)[8] = reinterpret_cast<float(*)[8]>(sbuf + 2048);    // overlays As
    const int col0 = blockIdx.x * 256;
    const int tid = threadIdx.x;
    const int wid = tid >> 5, lane = tid & 31;
    const int gID = lane >> 2, tig = lane & 3;
    const int n0w = wid * 32;
    float acc[4][4][4] = {};
    for (int k0 = 0; k0 < K; k0 += 64) {
        {
            int ar = tid >> 2, as = (tid & 3) * 16;
            *(uint4*)&As[ar][as]     = *(const uint4*)&A[(size_t)ar * K + k0 + as];
            *(uint4*)&As[ar][as + 8] = *(const uint4*)&A[(size_t)ar * K + k0 + as + 8];
            #pragma unroll
            for (int i = 0; i < 8; i++)
                *(uint4*)&Bs[tid][i * 8] = *(const uint4*)&B[(size_t)(col0 + tid) * K + k0 + i * 8];
        }
        __syncthreads();
        #pragma unroll
        for (int kk = 0; kk < 4; kk++) {
            const int kb = kk * 16;
            unsigned af[4][4], bf[4][2];
            #pragma unroll
            for (int mi = 0; mi < 4; mi++) {
                int r = mi * 16 + gID;
                int c = kb + tig * 2;
                af[mi][0] = *(const unsigned*)&As[r][c];
                af[mi][1] = *(const unsigned*)&As[r + 8][c];
                af[mi][2] = *(const unsigned*)&As[r][c + 8];
                af[mi][3] = *(const unsigned*)&As[r + 8][c + 8];
            }
            #pragma unroll
            for (int ni = 0; ni < 4; ni++) {
                int n = n0w + ni * 8 + gID;
                int c = kb + tig * 2;
                bf[ni][0] = *(const unsigned*)&Bs[n][c];
                bf[ni][1] = *(const unsigned*)&Bs[n][c + 8];
            }
            #pragma unroll
            for (int mi = 0; mi < 4; mi++)
                #pragma unroll
                for (int ni = 0; ni < 4; ni++)
                    mma_bf16(acc[mi][ni], af[mi], bf[ni]);
        }
        __syncthreads();
    }
    #pragma unroll
    for (int mi = 0; mi < 4; mi++) {
        const int r  = mi * 16 + gID;
        const int r2 = r + 8;
        const int tgt  = y[(t + 1) * Bn + r];
        const int tgt2 = y[(t + 1) * Bn + r2];
        float m1 = -1e30f, s1 = 0.f, m2 = -1e30f, s2 = 0.f;
        #pragma unroll
        for (int ni = 0; ni < 4; ni++) {
            int c = col0 + n0w + ni * 8 + tig * 2;
            float b0 = bias[c], b1 = bias[c + 1];
            float v0 = acc[mi][ni][0] + b0, v1 = acc[mi][ni][1] + b1;
            float v2 = acc[mi][ni][2] + b0, v3 = acc[mi][ni][3] + b1;
            if (c == tgt)      g_ltgt[r]  = v0;
            if (c + 1 == tgt)  g_ltgt[r]  = v1;
            if (c == tgt2)     g_ltgt[r2] = v2;
            if (c + 1 == tgt2) g_ltgt[r2] = v3;
            lse_upd(m1, s1, v0); lse_upd(m1, s1, v1);
            lse_upd(m2, s2, v2); lse_upd(m2, s2, v3);
        }
        #pragma unroll
        for (int off = 1; off <= 2; off <<= 1) {
            float om = __shfl_xor_sync(0xffffffffu, m1, off);
            float os = __shfl_xor_sync(0xffffffffu, s1, off);
            lse_comb(m1, s1, om, os);
            om = __shfl_xor_sync(0xffffffffu, m2, off);
            os = __shfl_xor_sync(0xffffffffu, s2, off);
            lse_comb(m2, s2, om, os);
        }
        if (tig == 0) {
            sm[r][wid] = m1; ss[r][wid] = s1;
            sm[r2][wid] = m2; ss[r2][wid] = s2;
        }
    }
    __syncthreads();
    if (tid < 64) {
        float M = sm[tid][0], S = ss[tid][0];
        #pragma unroll
        for (int w = 1; w < 8; w++) lse_comb(M, S, sm[tid][w], ss[tid][w]);
        g_pm[blockIdx.x * Bn + tid] = M;
        g_ps[blockIdx.x * Bn + tid] = S;
    }
}

// ============ fused attention + previous step's NLL finalize ==================
__global__ __launch_bounds__(256) void k_att(const float* __restrict__ mlp,
                                             const int* __restrict__ y, int t) {
    const int b = blockIdx.x;
    const int tid = threadIdx.x;
    const int wid = tid >> 5, lane = tid & 31;
    __shared__ float sc[200];
    __shared__ float red[8];
    if (t > 0 && wid == 7) {
        float m = -1e30f, s = 0.f;
        for (int i = lane; i < NVBLK; i += 32)
            lse_comb(m, s, g_pm[i * Bn + b], g_ps[i * Bn + b]);
        #pragma unroll
        for (int off = 16; off; off >>= 1) {
            float om = __shfl_xor_sync(0xffffffffu, m, off);
            float os = __shfl_xor_sync(0xffffffffu, s, off);
            lse_comb(m, s, om, os);
        }
        if (lane == 0) {
            int tgt = y[t * Bn + b];
            g_nll[(t - 1) * Bn + b] = (tgt != 0) ? (m + logf(s) - g_ltgt[b]) : 0.f;
        }
    }
    float hqv[32], mlpv[32];
    #pragma unroll
    for (int j = 0; j < 4; j++) {
        #pragma unroll
        for (int u = 0; u < 8; u++) {
            int m = lane * 8 + j * 256 + u;
            float v = g_hq_part[b * Cdim + m]
                    + g_hq_part[(Bn + b) * Cdim + m]
                    + g_hq_part[(2 * Bn + b) * Cdim + m]
                    + g_hq_part[(3 * Bn + b) * Cdim + m];
            hqv[j * 8 + u] = v;
            mlpv[j * 8 + u] = mlp[m];
        }
    }
    for (int s = wid; s < Sdim; s += 8) {
        const __nv_bfloat16* row = g_ctxp_bf16 + ((size_t)s * Bn + b) * Cdim;
        float sum = 0.f;
        #pragma unroll
        for (int j = 0; j < 4; j++) {
            int m = lane * 8 + j * 256;
            uint4 u = *(const uint4*)&row[m];
            float2 f0 = __bfloat1622float2(*(__nv_bfloat162*)&u.x);
            float2 f1 = __bfloat1622float2(*(__nv_bfloat162*)&u.y);
            float2 f2 = __bfloat1622float2(*(__nv_bfloat162*)&u.z);
            float2 f3 = __bfloat1622float2(*(__nv_bfloat162*)&u.w);
            sum += ftanh_fast(f0.x + hqv[j * 8 + 0]) * mlpv[j * 8 + 0];
            sum += ftanh_fast(f0.y + hqv[j * 8 + 1]) * mlpv[j * 8 + 1];
            sum += ftanh_fast(f1.x + hqv[j * 8 + 2]) * mlpv[j * 8 + 2];
            sum += ftanh_fast(f1.y + hqv[j * 8 + 3]) * mlpv[j * 8 + 3];
            sum += ftanh_fast(f2.x + hqv[j * 8 + 4]) * mlpv[j * 8 + 4];
            sum += ftanh_fast(f2.y + hqv[j * 8 + 5]) * mlpv[j * 8 + 5];
            sum += ftanh_fast(f3.x + hqv[j * 8 + 6]) * mlpv[j * 8 + 6];
            sum += ftanh_fast(f3.y + hqv[j * 8 + 7]) * mlpv[j * 8 + 7];
        }
        #pragma unroll
        for (int o = 16; o; o >>= 1) sum += __shfl_xor_sync(0xffffffffu, sum, o);
        if (lane == 0) sc[s] = sum;
    }
    __syncthreads();
    float v = (tid < Sdim) ? sc[tid] : -1e30f;
    float mx = blockReduceMax(v, red);
    float e = (tid < Sdim) ? __expf(v - mx) : 0.f;
    float tot = blockReduceSum(e, red);
    if (tid < Sdim) sc[tid] = __fdividef(e, tot);
    __syncthreads();
    const int c4 = tid * 4;
    float4 acc = make_float4(0.f, 0.f, 0.f, 0.f);
    #pragma unroll 4
    for (int s = 0; s < Sdim; s++) {
        float a = sc[s];
        uint2 u = *(const uint2*)&g_ctx_bf16[((size_t)s * Bn + b) * Cdim + c4];
        float2 f0 = __bfloat1622float2(*(__nv_bfloat162*)&u.x);
        float2 f1 = __bfloat1622float2(*(__nv_bfloat162*)&u.y);
        acc.x = fmaf(a, f0.x, acc.x); acc.y = fmaf(a, f0.y, acc.y);
        acc.z = fmaf(a, f1.x, acc.z); acc.w = fmaf(a, f1.y, acc.w);
    }
    *(float4*)&g_z[b * Cdim + c4] = acc;
}

// ---------------- per-step elementwise kernels --------------------------------
__global__ void k_gru(const float* __restrict__ b_ih, const float* __restrict__ b_hh) {
    const int i = blockIdx.x * 256 + threadIdx.x;
    const int b = i >> 10, j = i & (Hdim - 1);
    float ir = b_ih[j], iz = b_ih[Hdim + j], in_ = b_ih[2 * Hdim + j];
    #pragma unroll
    for (int p = 0; p < 4; p++) {
        const float* g = g_gi_part + ((size_t)p * Bn + b) * 3 * Hdim;
        ir += g[j]; iz += g[Hdim + j]; in_ += g[2 * Hdim + j];
    }
    float hr = b_hh[j], hz = b_hh[Hdim + j], hn = b_hh[2 * Hdim + j];
    #pragma unroll
    for (int p = 0; p < 4; p++) {
        const float* g = g_gh_part + ((size_t)p * Bn + b) * 3 * Hdim;
        hr += g[j]; hz += g[Hdim + j]; hn += g[2 * Hdim + j];
    }
    float r = fsig(ir + hr);
    float zz = fsig(iz + hz);
    float n = ftanh(in_ + r * hn);
    float hold = g_h[i];
    g_h[i] = (1.f - zz) * n + zz * hold;
}

// final: last step's NLL from partials + total sum
__global__ __launch_bounds__(256) void k_final(const int* __restrict__ y, float* __restrict__ out) {
    __shared__ float red[8];
    const int tid = threadIdx.x;
    if (tid < Bn) {
        float m = -1e30f, s = 0.f;
        for (int i = 0; i < NVBLK; i++)
            lse_comb(m, s, g_pm[i * Bn + tid], g_ps[i * Bn + tid]);
        int tgt = y[NSTEP * Bn + tid];
        g_nll[(NSTEP - 1) * Bn + tid] = (tgt != 0) ? (m + logf(s) - g_ltgt[tid]) : 0.f;
    }
    __syncthreads();
    float s = 0.f;
    for (int i = tid; i < NSTEP * Bn; i += 256) s += g_nll[i];
    float tot = blockReduceSum(s, red);
    if (tid == 0) out[0] = tot;
}

// ---------------- launch ------------------------------------------------------
extern "C" void kernel_launch(void* const* d_in, const int* in_sizes, int n_in,
                              void* d_out, int out_size) {
    const float* ctx         = (const float*)d_in[0];
    const int*   y           = (const int*)  d_in[1];
    const float* embW        = (const float*)d_in[2];
    const float* att_ctx2ctx = (const float*)d_in[3];
    const float* att_hid2ctx = (const float*)d_in[4];
    const float* att_mlp     = (const float*)d_in[5];
    const float* gru_W_ih    = (const float*)d_in[6];
    const float* gru_b_ih    = (const float*)d_in[7];
    const float* gru_W_hh    = (const float*)d_in[8];
    const float* gru_b_hh    = (const float*)d_in[9];
    const float* h2o_W       = (const float*)d_in[10];
    const float* h2o_b       = (const float*)d_in[11];
    const float* octx_W      = (const float*)d_in[12];
    const float* octx_b      = (const float*)d_in[13];
    const float* o2p_W       = (const float*)d_in[14];
    const float* o2p_b       = (const float*)d_in[15];

    float *p_h, *p_hqp, *p_gip, *p_ghp;
    __nv_bfloat16 *p_ctxpbf, *p_ctxbf, *p_WctxTbf, *p_WhidTbf, *p_Wihbf, *p_Whhbf,
                  *p_h2obf, *p_octxbf, *p_Wbf, *p_pbf;
    cudaGetSymbolAddress((void**)&p_ctxpbf,  g_ctxp_bf16);
    cudaGetSymbolAddress((void**)&p_ctxbf,   g_ctx_bf16);
    cudaGetSymbolAddress((void**)&p_WctxTbf, g_WctxT_bf16);
    cudaGetSymbolAddress((void**)&p_WhidTbf, g_WhidT_bf16);
    cudaGetSymbolAddress((void**)&p_Wihbf,   g_Wih_bf16);
    cudaGetSymbolAddress((void**)&p_Whhbf,   g_Whh_bf16);
    cudaGetSymbolAddress((void**)&p_h2obf,   g_h2o_bf16);
    cudaGetSymbolAddress((void**)&p_octxbf,  g_octx_bf16);
    cudaGetSymbolAddress((void**)&p_Wbf,     g_Wo2p_bf16);
    cudaGetSymbolAddress((void**)&p_pbf,     g_p_bf16);
    cudaGetSymbolAddress((void**)&p_h,       g_h);
    cudaGetSymbolAddress((void**)&p_hqp,     g_hq_part);
    cudaGetSymbolAddress((void**)&p_gip,     g_gi_part);
    cudaGetSymbolAddress((void**)&p_ghp,     g_gh_part);

    // one-time prep
    k_cvt_all<<<(unsigned)((CVT_N5 + 255) / 256), 256>>>(ctx, gru_W_ih, gru_W_hh,
                                                         h2o_W, octx_W, o2p_W);
    k_transpose_bf16<<<dim3(32, 32), dim3(32, 8)>>>(att_ctx2ctx, p_WctxTbf, Cdim, Cdim);
    k_transpose_bf16<<<dim3(32, 32), dim3(32, 8)>>>(att_hid2ctx, p_WhidTbf, Hdim, Cdim);
    k_zero_init<<<(Bn * Hdim + 4 * Bn * Cdim) / 256, 256>>>();
    gemm_bf16_m128<<<dim3(Cdim / 128, (Sdim * Bn) / 128), 256>>>(
        p_ctxbf, p_WctxTbf, p_ctxpbf, Cdim, Cdim);

    for (int t = 0; t < NSTEP; t++) {
        k_att<<<Bn, 256>>>(att_mlp, y, t);
        gemm_bf16_gigh_sk<<<dim3((3 * Hdim) / 64, 2, 4), 256>>>(
            embW, y, t, p_Wihbf, p_gip, p_Whhbf, p_ghp);
        k_gru<<<(Bn * Hdim) / 256, 256>>>(gru_b_ih, gru_b_hh);
        // hq (next step, split-K4) + fused o1/o2 -> p, one launch
        gemm_bf16_hq_o1o2p<<<dim3(Cdim / 64, 2, 4), 256>>>(
            p_h, y, t, embW, p_h2obf, p_octxbf, p_WhidTbf, h2o_b, octx_b, p_hqp);
        gemm_bf16_logits_nll<<<NVBLK, 256>>>(p_pbf, p_Wbf, o2p_b, y, t, Edim);
    }
    k_final<<<1, 256>>>(y, (float*)d_out);
}

// round 14
// speedup vs baseline: 1.2967x; 1.2967x over previous
#include <cuda_runtime.h>
#include <cuda_bf16.h>
#include <math.h>

#define Sdim 196
#define Bn   64
#define Cdim 1024
#define Hdim 1024
#define Edim 512
#define Vdim 32000
#define NSTEP 19
#define NVBLK (Vdim / 256)   // 125 logits blocks

// ---------------- scratch (device globals) -----------------------------------
__device__ __nv_bfloat16 g_ctxp_bf16[(size_t)Sdim * Bn * Cdim];
__device__ __nv_bfloat16 g_ctx_bf16[(size_t)Sdim * Bn * Cdim];
__device__ __nv_bfloat16 g_WctxT_bf16[Cdim * Cdim];
__device__ __nv_bfloat16 g_WhidT_bf16[Hdim * Cdim];
__device__ __nv_bfloat16 g_Wih_bf16[3 * Hdim * (Edim + Cdim)];
__device__ __nv_bfloat16 g_Whh_bf16[3 * Hdim * Hdim];
__device__ __nv_bfloat16 g_h2o_bf16[Edim * Hdim];
__device__ __nv_bfloat16 g_octx_bf16[Edim * Cdim];
__device__ __nv_bfloat16 g_Wo2p_bf16[(size_t)Vdim * Edim];
__device__ __nv_bfloat16 g_p_bf16[Bn * Edim];
__device__ float g_h[Bn * Hdim];
__device__ float g_hq_part[4 * Bn * Cdim];
__device__ float g_z[Bn * Cdim];
__device__ float g_gi_part[4 * Bn * 3 * Hdim];
__device__ float g_gh_part[4 * Bn * 3 * Hdim];
__device__ float g_o1_part[4 * Bn * Edim];
__device__ float g_o2_part[4 * Bn * Edim];
__device__ float g_pm[NVBLK * Bn];
__device__ float g_ps[NVBLK * Bn];
__device__ float g_ltgt[Bn];
__device__ float g_nll[NSTEP * Bn];

// ---------------- fast math ---------------------------------------------------
__device__ __forceinline__ float ftanh(float x) {
    float xc = fminf(fmaxf(x, -15.f), 15.f);
    float e = __expf(2.f * xc);
    return __fdividef(e - 1.f, e + 1.f);
}
__device__ __forceinline__ float ftanh_fast(float x) {
    float y;
    asm("tanh.approx.f32 %0, %1;" : "=f"(y) : "f"(x));
    return y;
}
__device__ __forceinline__ float fsig(float x) {
    return __fdividef(1.f, 1.f + __expf(-x));
}
__device__ __forceinline__ void mma_bf16(float* d, const unsigned* a4, const unsigned* b2) {
    asm volatile(
        "mma.sync.aligned.m16n8k16.row.col.f32.bf16.bf16.f32 "
        "{%0,%1,%2,%3}, {%4,%5,%6,%7}, {%8,%9}, {%0,%1,%2,%3};\n"
        : "+f"(d[0]), "+f"(d[1]), "+f"(d[2]), "+f"(d[3])
        : "r"(a4[0]), "r"(a4[1]), "r"(a4[2]), "r"(a4[3]), "r"(b2[0]), "r"(b2[1]));
}
__device__ __forceinline__ void lse_upd(float& m, float& s, float v) {
    if (v > m) { s = s * __expf(m - v) + 1.f; m = v; }
    else       { s += __expf(v - m); }
}
__device__ __forceinline__ void lse_comb(float& m, float& s, float m2, float s2) {
    float M = fmaxf(m, m2);
    s = s * __expf(m - M) + s2 * __expf(m2 - M);
    m = M;
}

// ---------------- block reductions (fixed order) ------------------------------
__device__ __forceinline__ float blockReduceSum(float v, float* red) {
    #pragma unroll
    for (int o = 16; o; o >>= 1) v += __shfl_xor_sync(0xffffffffu, v, o);
    if ((threadIdx.x & 31) == 0) red[threadIdx.x >> 5] = v;
    __syncthreads();
    float t = 0.f;
    int nw = blockDim.x >> 5;
    for (int i = 0; i < nw; i++) t += red[i];
    __syncthreads();
    return t;
}
__device__ __forceinline__ float blockReduceMax(float v, float* red) {
    #pragma unroll
    for (int o = 16; o; o >>= 1) v = fmaxf(v, __shfl_xor_sync(0xffffffffu, v, o));
    if ((threadIdx.x & 31) == 0) red[threadIdx.x >> 5] = v;
    __syncthreads();
    float t = red[0];
    int nw = blockDim.x >> 5;
    for (int i = 1; i < nw; i++) t = fmaxf(t, red[i]);
    __syncthreads();
    return t;
}

// ---------------- one-time prep kernels ---------------------------------------
__global__ void k_transpose_bf16(const float* __restrict__ in, __nv_bfloat16* __restrict__ out, int R, int Ccols) {
    __shared__ float t[32][33];
    int c0 = blockIdx.x * 32, r0 = blockIdx.y * 32;
    #pragma unroll
    for (int i = 0; i < 4; i++)
        t[threadIdx.y + i * 8][threadIdx.x] = in[(size_t)(r0 + threadIdx.y + i * 8) * Ccols + c0 + threadIdx.x];
    __syncthreads();
    #pragma unroll
    for (int i = 0; i < 4; i++)
        out[(size_t)(c0 + threadIdx.y + i * 8) * R + r0 + threadIdx.x] =
            __float2bfloat16_rn(t[threadIdx.x][threadIdx.y + i * 8]);
}

// all plain fp32->bf16 conversions + zero-init in one launch (float4 index)
#define CVT_N0 ((size_t)Sdim * Bn * Cdim / 4)
#define CVT_N1 (CVT_N0 + (size_t)3 * Hdim * (Edim + Cdim) / 4)
#define CVT_N2 (CVT_N1 + (size_t)3 * Hdim * Hdim / 4)
#define CVT_N3 (CVT_N2 + (size_t)Edim * Hdim / 4)
#define CVT_N4 (CVT_N3 + (size_t)Edim * Cdim / 4)
#define CVT_N5 (CVT_N4 + (size_t)Vdim * Edim / 4)
#define CVT_N6 (CVT_N5 + (size_t)(Bn * Hdim) / 4)        // zero g_h
#define CVT_N7 (CVT_N6 + (size_t)(4 * Bn * Cdim) / 4)    // zero g_hq_part
__global__ void k_cvt_all(const float* __restrict__ ctx, const float* __restrict__ Wih,
                          const float* __restrict__ Whh, const float* __restrict__ h2o,
                          const float* __restrict__ octx, const float* __restrict__ o2p) {
    size_t i = (size_t)blockIdx.x * 256 + threadIdx.x;   // float4 index
    if (i >= CVT_N7) return;
    if (i >= CVT_N5) {
        float4 zz = make_float4(0.f, 0.f, 0.f, 0.f);
        if (i < CVT_N6) *(float4*)&g_h[(i - CVT_N5) * 4] = zz;
        else            *(float4*)&g_hq_part[(i - CVT_N6) * 4] = zz;
        return;
    }
    const float* src; __nv_bfloat16* dst; size_t off;
    if      (i < CVT_N0) { src = ctx;  dst = g_ctx_bf16;  off = i; }
    else if (i < CVT_N1) { src = Wih;  dst = g_Wih_bf16;  off = i - CVT_N0; }
    else if (i < CVT_N2) { src = Whh;  dst = g_Whh_bf16;  off = i - CVT_N1; }
    else if (i < CVT_N3) { src = h2o;  dst = g_h2o_bf16;  off = i - CVT_N2; }
    else if (i < CVT_N4) { src = octx; dst = g_octx_bf16; off = i - CVT_N3; }
    else                 { src = o2p;  dst = g_Wo2p_bf16; off = i - CVT_N4; }
    float4 v = *(const float4*)&src[off * 4];
    __nv_bfloat162* o = (__nv_bfloat162*)&dst[off * 4];
    o[0] = __floats2bfloat162_rn(v.x, v.y);
    o[1] = __floats2bfloat162_rn(v.z, v.w);
}

// ============ BF16 NT GEMM, 128x128 tile, bf16 out, reg-pipelined (ctx_proj) ==
__global__ __launch_bounds__(256) void gemm_bf16_m128(
    const __nv_bfloat16* __restrict__ A, const __nv_bfloat16* __restrict__ B,
    __nv_bfloat16* __restrict__ C, int N, int K) {
    __shared__ __nv_bfloat16 As[128][72];
    __shared__ __nv_bfloat16 Bs[128][72];
    const int row0 = blockIdx.y * 128, col0 = blockIdx.x * 128;
    const int tid = threadIdx.x;
    const int wid = tid >> 5, lane = tid & 31;
    const int gID = lane >> 2, tig = lane & 3;
    const int m0w = (wid >> 2) * 64, n0w = (wid & 3) * 32;
    const int lrow = tid >> 1, lcol = (tid & 1) * 32;
    float acc[4][4][4] = {};
    uint4 ra[4], rb[4];
    #pragma unroll
    for (int i = 0; i < 4; i++) {
        ra[i] = *(const uint4*)&A[(size_t)(row0 + lrow) * K + lcol + i * 8];
        rb[i] = *(const uint4*)&B[(size_t)(col0 + lrow) * K + lcol + i * 8];
    }
    for (int k0 = 0; k0 < K; k0 += 64) {
        #pragma unroll
        for (int i = 0; i < 4; i++) {
            *(uint4*)&As[lrow][lcol + i * 8] = ra[i];
            *(uint4*)&Bs[lrow][lcol + i * 8] = rb[i];
        }
        __syncthreads();
        if (k0 + 64 < K) {
            #pragma unroll
            for (int i = 0; i < 4; i++) {
                ra[i] = *(const uint4*)&A[(size_t)(row0 + lrow) * K + k0 + 64 + lcol + i * 8];
                rb[i] = *(const uint4*)&B[(size_t)(col0 + lrow) * K + k0 + 64 + lcol + i * 8];
            }
        }
        #pragma unroll
        for (int kk = 0; kk < 4; kk++) {
            const int kb = kk * 16;
            unsigned af[4][4], bf[4][2];
            #pragma unroll
            for (int mi = 0; mi < 4; mi++) {
                int r = m0w + mi * 16 + gID;
                int c = kb + tig * 2;
                af[mi][0] = *(const unsigned*)&As[r][c];
                af[mi][1] = *(const unsigned*)&As[r + 8][c];
                af[mi][2] = *(const unsigned*)&As[r][c + 8];
                af[mi][3] = *(const unsigned*)&As[r + 8][c + 8];
            }
            #pragma unroll
            for (int ni = 0; ni < 4; ni++) {
                int n = n0w + ni * 8 + gID;
                int c = kb + tig * 2;
                bf[ni][0] = *(const unsigned*)&Bs[n][c];
                bf[ni][1] = *(const unsigned*)&Bs[n][c + 8];
            }
            #pragma unroll
            for (int mi = 0; mi < 4; mi++)
                #pragma unroll
                for (int ni = 0; ni < 4; ni++)
                    mma_bf16(acc[mi][ni], af[mi], bf[ni]);
        }
        __syncthreads();
    }
    #pragma unroll
    for (int mi = 0; mi < 4; mi++)
        #pragma unroll
        for (int ni = 0; ni < 4; ni++) {
            int r = row0 + m0w + mi * 16 + gID;
            int c = col0 + n0w + ni * 8 + tig * 2;
            *(__nv_bfloat162*)&C[(size_t)r * N + c]       = __floats2bfloat162_rn(acc[mi][ni][0], acc[mi][ni][1]);
            *(__nv_bfloat162*)&C[(size_t)(r + 8) * N + c] = __floats2bfloat162_rn(acc[mi][ni][2], acc[mi][ni][3]);
        }
}

// ============ BF16 triple GEMM (o1, o2, hq-next), M=64, split-K ===============
// blockIdx.y: 0 -> o1 = h @ h2o^T (N=Edim); 1 -> o2 = z @ octx^T (N=Edim);
//             2 -> hq = h @ WhidT^T (N=Cdim).  All K=Hdim, split-K4.
__global__ __launch_bounds__(256) void gemm_bf16_m64_tri(
    const float* __restrict__ h, const float* __restrict__ z,
    const __nv_bfloat16* __restrict__ Bh2o, const __nv_bfloat16* __restrict__ Boctx,
    const __nv_bfloat16* __restrict__ Bhid,
    float* __restrict__ Co1, float* __restrict__ Co2, float* __restrict__ Chq) {
    const int prob = blockIdx.y;
    const float* A; const __nv_bfloat16* B; float* C; int N;
    if (prob == 0)      { A = h; B = Bh2o;  C = Co1; N = Edim; }
    else if (prob == 1) { A = z; B = Boctx; C = Co2; N = Edim; }
    else                { A = h; B = Bhid;  C = Chq; N = Cdim; }
    const int col0 = blockIdx.x * 64;
    if (col0 >= N) return;
    const int K = Hdim, kChunk = Hdim / 4;
    __shared__ __nv_bfloat16 As[64][72];
    __shared__ __nv_bfloat16 Bs[64][72];
    const int kbase = blockIdx.z * kChunk;
    const int tid = threadIdx.x;
    const int wid = tid >> 5, lane = tid & 31;
    const int gID = lane >> 2, tig = lane & 3;
    const int lrow = tid >> 2, lseg = (tid & 3) * 16;
    float acc[4][4] = {};
    for (int kt = 0; kt < kChunk; kt += 64) {
        const int k0 = kbase + kt;
        #pragma unroll
        for (int i = 0; i < 4; i++) {
            float4 a = *(const float4*)&A[(size_t)lrow * K + k0 + lseg + i * 4];
            __nv_bfloat162* d = (__nv_bfloat162*)&As[lrow][lseg + i * 4];
            d[0] = __floats2bfloat162_rn(a.x, a.y);
            d[1] = __floats2bfloat162_rn(a.z, a.w);
        }
        *(uint4*)&Bs[lrow][lseg]     = *(const uint4*)&B[(size_t)(col0 + lrow) * K + k0 + lseg];
        *(uint4*)&Bs[lrow][lseg + 8] = *(const uint4*)&B[(size_t)(col0 + lrow) * K + k0 + lseg + 8];
        __syncthreads();
        #pragma unroll
        for (int kk = 0; kk < 4; kk++) {
            const int c = kk * 16 + tig * 2;
            const int n = wid * 8 + gID;
            unsigned bfv[2];
            bfv[0] = *(const unsigned*)&Bs[n][c];
            bfv[1] = *(const unsigned*)&Bs[n][c + 8];
            #pragma unroll
            for (int mi = 0; mi < 4; mi++) {
                int r = mi * 16 + gID;
                unsigned af[4];
                af[0] = *(const unsigned*)&As[r][c];
                af[1] = *(const unsigned*)&As[r + 8][c];
                af[2] = *(const unsigned*)&As[r][c + 8];
                af[3] = *(const unsigned*)&As[r + 8][c + 8];
                mma_bf16(acc[mi], af, bfv);
            }
        }
        __syncthreads();
    }
    float* Cp = C + (size_t)blockIdx.z * 64 * N;
    #pragma unroll
    for (int mi = 0; mi < 4; mi++) {
        int r = mi * 16 + gID;
        int c = col0 + wid * 8 + tig * 2;
        *(float2*)&Cp[(size_t)r * N + c]       = make_float2(acc[mi][0], acc[mi][1]);
        *(float2*)&Cp[(size_t)(r + 8) * N + c] = make_float2(acc[mi][2], acc[mi][3]);
    }
}

// ============ merged GRU GEMMs (bf16): y=0 -> gi (A gathered), y=1 -> gh ======
__global__ __launch_bounds__(256) void gemm_bf16_gigh_sk(
    const float* __restrict__ embW, const int* __restrict__ y, int t,
    const __nv_bfloat16* __restrict__ Wih, float* __restrict__ Cgi,
    const __nv_bfloat16* __restrict__ Whh, float* __restrict__ Cgh) {
    const bool is_gi = (blockIdx.y == 0);
    const int K      = is_gi ? (Edim + Cdim) : Hdim;
    const int kChunk = is_gi ? ((Edim + Cdim) / 4) : (Hdim / 4);
    const __nv_bfloat16* B = is_gi ? Wih : Whh;
    float* C = is_gi ? Cgi : Cgh;
    const int N = 3 * Hdim;
    __shared__ __nv_bfloat16 As[64][72];
    __shared__ __nv_bfloat16 Bs[64][72];
    const int col0 = blockIdx.x * 64;
    const int kbase = blockIdx.z * kChunk;
    const int tid = threadIdx.x;
    const int wid = tid >> 5, lane = tid & 31;
    const int gID = lane >> 2, tig = lane & 3;
    const int lrow = tid >> 2, lseg = (tid & 3) * 16;
    const int yid = is_gi ? y[t * Bn + lrow] : 0;
    float acc[4][4] = {};
    for (int kt = 0; kt < kChunk; kt += 64) {
        const int k0 = kbase + kt;
        const float* Arow;
        if (is_gi) Arow = (k0 < Edim) ? &embW[(size_t)yid * Edim + k0]
                                      : &g_z[lrow * Cdim + (k0 - Edim)];
        else       Arow = &g_h[lrow * Hdim + k0];
        #pragma unroll
        for (int i = 0; i < 4; i++) {
            float4 a = *(const float4*)&Arow[lseg + i * 4];
            __nv_bfloat162* d = (__nv_bfloat162*)&As[lrow][lseg + i * 4];
            d[0] = __floats2bfloat162_rn(a.x, a.y);
            d[1] = __floats2bfloat162_rn(a.z, a.w);
        }
        *(uint4*)&Bs[lrow][lseg]     = *(const uint4*)&B[(size_t)(col0 + lrow) * K + k0 + lseg];
        *(uint4*)&Bs[lrow][lseg + 8] = *(const uint4*)&B[(size_t)(col0 + lrow) * K + k0 + lseg + 8];
        __syncthreads();
        #pragma unroll
        for (int kk = 0; kk < 4; kk++) {
            const int c = kk * 16 + tig * 2;
            const int n = wid * 8 + gID;
            unsigned bfv[2];
            bfv[0] = *(const unsigned*)&Bs[n][c];
            bfv[1] = *(const unsigned*)&Bs[n][c + 8];
            #pragma unroll
            for (int mi = 0; mi < 4; mi++) {
                int r = mi * 16 + gID;
                unsigned af[4];
                af[0] = *(const unsigned*)&As[r][c];
                af[1] = *(const unsigned*)&As[r + 8][c];
                af[2] = *(const unsigned*)&As[r][c + 8];
                af[3] = *(const unsigned*)&As[r + 8][c + 8];
                mma_bf16(acc[mi], af, bfv);
            }
        }
        __syncthreads();
    }
    float* Cp = C + (size_t)blockIdx.z * 64 * N;
    #pragma unroll
    for (int mi = 0; mi < 4; mi++) {
        int r = mi * 16 + gID;
        int c = col0 + wid * 8 + tig * 2;
        *(float2*)&Cp[(size_t)r * N + c]       = make_float2(acc[mi][0], acc[mi][1]);
        *(float2*)&Cp[(size_t)(r + 8) * N + c] = make_float2(acc[mi][2], acc[mi][3]);
    }
}

// ============ BF16 logits GEMM + fused partial NLL ============================
__global__ __launch_bounds__(256) void gemm_bf16_logits_nll(
    const __nv_bfloat16* __restrict__ A, const __nv_bfloat16* __restrict__ B,
    const float* __restrict__ bias, const int* __restrict__ y, int t, int K) {
    __shared__ __align__(16) unsigned char sbuf[9216 + 36864];
    __nv_bfloat16 (*As)[72] = reinterpret_cast<__nv_bfloat16(*)[72]>(sbuf);
    __nv_bfloat16 (*Bs)[72] = reinterpret_cast<__nv_bfloat16(*)[72]>(sbuf + 9216);
    float (*sm)[8] = reinterpret_cast<float(*)[8]>(sbuf);           // overlays As
    float (*ss)[8] = reinterpret_cast<float(*)[8]>(sbuf + 2048);    // overlays As
    const int col0 = blockIdx.x * 256;
    const int tid = threadIdx.x;
    const int wid = tid >> 5, lane = tid & 31;
    const int gID = lane >> 2, tig = lane & 3;
    const int n0w = wid * 32;
    float acc[4][4][4] = {};
    for (int k0 = 0; k0 < K; k0 += 64) {
        {
            int ar = tid >> 2, as = (tid & 3) * 16;
            *(uint4*)&As[ar][as]     = *(const uint4*)&A[(size_t)ar * K + k0 + as];
            *(uint4*)&As[ar][as + 8] = *(const uint4*)&A[(size_t)ar * K + k0 + as + 8];
            #pragma unroll
            for (int i = 0; i < 8; i++)
                *(uint4*)&Bs[tid][i * 8] = *(const uint4*)&B[(size_t)(col0 + tid) * K + k0 + i * 8];
        }
        __syncthreads();
        #pragma unroll
        for (int kk = 0; kk < 4; kk++) {
            const int kb = kk * 16;
            unsigned af[4][4], bf[4][2];
            #pragma unroll
            for (int mi = 0; mi < 4; mi++) {
                int r = mi * 16 + gID;
                int c = kb + tig * 2;
                af[mi][0] = *(const unsigned*)&As[r][c];
                af[mi][1] = *(const unsigned*)&As[r + 8][c];
                af[mi][2] = *(const unsigned*)&As[r][c + 8];
                af[mi][3] = *(const unsigned*)&As[r + 8][c + 8];
            }
            #pragma unroll
            for (int ni = 0; ni < 4; ni++) {
                int n = n0w + ni * 8 + gID;
                int c = kb + tig * 2;
                bf[ni][0] = *(const unsigned*)&Bs[n][c];
                bf[ni][1] = *(const unsigned*)&Bs[n][c + 8];
            }
            #pragma unroll
            for (int mi = 0; mi < 4; mi++)
                #pragma unroll
                for (int ni = 0; ni < 4; ni++)
                    mma_bf16(acc[mi][ni], af[mi], bf[ni]);
        }
        __syncthreads();
    }
    #pragma unroll
    for (int mi = 0; mi < 4; mi++) {
        const int r  = mi * 16 + gID;
        const int r2 = r + 8;
        const int tgt  = y[(t + 1) * Bn + r];
        const int tgt2 = y[(t + 1) * Bn + r2];
        float m1 = -1e30f, s1 = 0.f, m2 = -1e30f, s2 = 0.f;
        #pragma unroll
        for (int ni = 0; ni < 4; ni++) {
            int c = col0 + n0w + ni * 8 + tig * 2;
            float b0 = bias[c], b1 = bias[c + 1];
            float v0 = acc[mi][ni][0] + b0, v1 = acc[mi][ni][1] + b1;
            float v2 = acc[mi][ni][2] + b0, v3 = acc[mi][ni][3] + b1;
            if (c == tgt)      g_ltgt[r]  = v0;
            if (c + 1 == tgt)  g_ltgt[r]  = v1;
            if (c == tgt2)     g_ltgt[r2] = v2;
            if (c + 1 == tgt2) g_ltgt[r2] = v3;
            lse_upd(m1, s1, v0); lse_upd(m1, s1, v1);
            lse_upd(m2, s2, v2); lse_upd(m2, s2, v3);
        }
        #pragma unroll
        for (int off = 1; off <= 2; off <<= 1) {
            float om = __shfl_xor_sync(0xffffffffu, m1, off);
            float os = __shfl_xor_sync(0xffffffffu, s1, off);
            lse_comb(m1, s1, om, os);
            om = __shfl_xor_sync(0xffffffffu, m2, off);
            os = __shfl_xor_sync(0xffffffffu, s2, off);
            lse_comb(m2, s2, om, os);
        }
        if (tig == 0) {
            sm[r][wid] = m1; ss[r][wid] = s1;
            sm[r2][wid] = m2; ss[r2][wid] = s2;
        }
    }
    __syncthreads();
    if (tid < 64) {
        float M = sm[tid][0], S = ss[tid][0];
        #pragma unroll
        for (int w = 1; w < 8; w++) lse_comb(M, S, sm[tid][w], ss[tid][w]);
        g_pm[blockIdx.x * Bn + tid] = M;
        g_ps[blockIdx.x * Bn + tid] = S;
    }
}

// ============ fused attention + previous step's NLL finalize ==================
__global__ __launch_bounds__(256) void k_att(const float* __restrict__ mlp,
                                             const int* __restrict__ y, int t) {
    const int b = blockIdx.x;
    const int tid = threadIdx.x;
    const int wid = tid >> 5, lane = tid & 31;
    __shared__ float sc[200];
    __shared__ float red[8];
    if (t > 0 && wid == 7) {
        float m = -1e30f, s = 0.f;
        for (int i = lane; i < NVBLK; i += 32)
            lse_comb(m, s, g_pm[i * Bn + b], g_ps[i * Bn + b]);
        #pragma unroll
        for (int off = 16; off; off >>= 1) {
            float om = __shfl_xor_sync(0xffffffffu, m, off);
            float os = __shfl_xor_sync(0xffffffffu, s, off);
            lse_comb(m, s, om, os);
        }
        if (lane == 0) {
            int tgt = y[t * Bn + b];
            g_nll[(t - 1) * Bn + b] = (tgt != 0) ? (m + logf(s) - g_ltgt[b]) : 0.f;
        }
    }
    float hqv[32], mlpv[32];
    #pragma unroll
    for (int j = 0; j < 4; j++) {
        #pragma unroll
        for (int u = 0; u < 8; u++) {
            int m = lane * 8 + j * 256 + u;
            float v = g_hq_part[b * Cdim + m]
                    + g_hq_part[(Bn + b) * Cdim + m]
                    + g_hq_part[(2 * Bn + b) * Cdim + m]
                    + g_hq_part[(3 * Bn + b) * Cdim + m];
            hqv[j * 8 + u] = v;
            mlpv[j * 8 + u] = mlp[m];
        }
    }
    for (int s = wid; s < Sdim; s += 8) {
        const __nv_bfloat16* row = g_ctxp_bf16 + ((size_t)s * Bn + b) * Cdim;
        float sum = 0.f;
        #pragma unroll
        for (int j = 0; j < 4; j++) {
            int m = lane * 8 + j * 256;
            uint4 u = *(const uint4*)&row[m];
            float2 f0 = __bfloat1622float2(*(__nv_bfloat162*)&u.x);
            float2 f1 = __bfloat1622float2(*(__nv_bfloat162*)&u.y);
            float2 f2 = __bfloat1622float2(*(__nv_bfloat162*)&u.z);
            float2 f3 = __bfloat1622float2(*(__nv_bfloat162*)&u.w);
            sum += ftanh_fast(f0.x + hqv[j * 8 + 0]) * mlpv[j * 8 + 0];
            sum += ftanh_fast(f0.y + hqv[j * 8 + 1]) * mlpv[j * 8 + 1];
            sum += ftanh_fast(f1.x + hqv[j * 8 + 2]) * mlpv[j * 8 + 2];
            sum += ftanh_fast(f1.y + hqv[j * 8 + 3]) * mlpv[j * 8 + 3];
            sum += ftanh_fast(f2.x + hqv[j * 8 + 4]) * mlpv[j * 8 + 4];
            sum += ftanh_fast(f2.y + hqv[j * 8 + 5]) * mlpv[j * 8 + 5];
            sum += ftanh_fast(f3.x + hqv[j * 8 + 6]) * mlpv[j * 8 + 6];
            sum += ftanh_fast(f3.y + hqv[j * 8 + 7]) * mlpv[j * 8 + 7];
        }
        #pragma unroll
        for (int o = 16; o; o >>= 1) sum += __shfl_xor_sync(0xffffffffu, sum, o);
        if (lane == 0) sc[s] = sum;
    }
    __syncthreads();
    float v = (tid < Sdim) ? sc[tid] : -1e30f;
    float mx = blockReduceMax(v, red);
    float e = (tid < Sdim) ? __expf(v - mx) : 0.f;
    float tot = blockReduceSum(e, red);
    if (tid < Sdim) sc[tid] = __fdividef(e, tot);
    __syncthreads();
    const int c4 = tid * 4;
    float4 acc = make_float4(0.f, 0.f, 0.f, 0.f);
    #pragma unroll 4
    for (int s = 0; s < Sdim; s++) {
        float a = sc[s];
        uint2 u = *(const uint2*)&g_ctx_bf16[((size_t)s * Bn + b) * Cdim + c4];
        float2 f0 = __bfloat1622float2(*(__nv_bfloat162*)&u.x);
        float2 f1 = __bfloat1622float2(*(__nv_bfloat162*)&u.y);
        acc.x = fmaf(a, f0.x, acc.x); acc.y = fmaf(a, f0.y, acc.y);
        acc.z = fmaf(a, f1.x, acc.z); acc.w = fmaf(a, f1.y, acc.w);
    }
    *(float4*)&g_z[b * Cdim + c4] = acc;
}

// ---------------- per-step elementwise kernels --------------------------------
__global__ void k_gru(const float* __restrict__ b_ih, const float* __restrict__ b_hh) {
    const int i = blockIdx.x * 256 + threadIdx.x;
    const int b = i >> 10, j = i & (Hdim - 1);
    float ir = b_ih[j], iz = b_ih[Hdim + j], in_ = b_ih[2 * Hdim + j];
    #pragma unroll
    for (int p = 0; p < 4; p++) {
        const float* g = g_gi_part + ((size_t)p * Bn + b) * 3 * Hdim;
        ir += g[j]; iz += g[Hdim + j]; in_ += g[2 * Hdim + j];
    }
    float hr = b_hh[j], hz = b_hh[Hdim + j], hn = b_hh[2 * Hdim + j];
    #pragma unroll
    for (int p = 0; p < 4; p++) {
        const float* g = g_gh_part + ((size_t)p * Bn + b) * 3 * Hdim;
        hr += g[j]; hz += g[Hdim + j]; hn += g[2 * Hdim + j];
    }
    float r = fsig(ir + hr);
    float zz = fsig(iz + hz);
    float n = ftanh(in_ + r * hn);
    float hold = g_h[i];
    g_h[i] = (1.f - zz) * n + zz * hold;
}

__global__ void k_pvec(const float* __restrict__ embW, const int* __restrict__ y,
                       const float* __restrict__ h2o_b, const float* __restrict__ octx_b, int t) {
    const int i = blockIdx.x * 256 + threadIdx.x;
    const int b = i >> 9, e = i & (Edim - 1);
    float o1 = h2o_b[e], o2 = octx_b[e];
    #pragma unroll
    for (int p = 0; p < 4; p++) {
        o1 += g_o1_part[p * Bn * Edim + i];
        o2 += g_o2_part[p * Bn * Edim + i];
    }
    float l = ftanh(o1);
    l += embW[(size_t)y[t * Bn + b] * Edim + e];
    l += o2;
    g_p_bf16[i] = __float2bfloat16_rn(ftanh(l));
}

// final: last step's NLL from partials + total sum
__global__ __launch_bounds__(256) void k_final(const int* __restrict__ y, float* __restrict__ out) {
    __shared__ float red[8];
    const int tid = threadIdx.x;
    if (tid < Bn) {
        float m = -1e30f, s = 0.f;
        for (int i = 0; i < NVBLK; i++)
            lse_comb(m, s, g_pm[i * Bn + tid], g_ps[i * Bn + tid]);
        int tgt = y[NSTEP * Bn + tid];
        g_nll[(NSTEP - 1) * Bn + tid] = (tgt != 0) ? (m + logf(s) - g_ltgt[tid]) : 0.f;
    }
    __syncthreads();
    float s = 0.f;
    for (int i = tid; i < NSTEP * Bn; i += 256) s += g_nll[i];
    float tot = blockReduceSum(s, red);
    if (tid == 0) out[0] = tot;
}

// ---------------- launch ------------------------------------------------------
extern "C" void kernel_launch(void* const* d_in, const int* in_sizes, int n_in,
                              void* d_out, int out_size) {
    const float* ctx         = (const float*)d_in[0];
    const int*   y           = (const int*)  d_in[1];
    const float* embW        = (const float*)d_in[2];
    const float* att_ctx2ctx = (const float*)d_in[3];
    const float* att_hid2ctx = (const float*)d_in[4];
    const float* att_mlp     = (const float*)d_in[5];
    const float* gru_W_ih    = (const float*)d_in[6];
    const float* gru_b_ih    = (const float*)d_in[7];
    const float* gru_W_hh    = (const float*)d_in[8];
    const float* gru_b_hh    = (const float*)d_in[9];
    const float* h2o_W       = (const float*)d_in[10];
    const float* h2o_b       = (const float*)d_in[11];
    const float* octx_W      = (const float*)d_in[12];
    const float* octx_b      = (const float*)d_in[13];
    const float* o2p_W       = (const float*)d_in[14];
    const float* o2p_b       = (const float*)d_in[15];

    float *p_h, *p_hqp, *p_z, *p_gip, *p_ghp, *p_o1p, *p_o2p;
    __nv_bfloat16 *p_ctxpbf, *p_ctxbf, *p_WctxTbf, *p_WhidTbf, *p_Wihbf, *p_Whhbf,
                  *p_h2obf, *p_octxbf, *p_Wbf, *p_pbf;
    cudaGetSymbolAddress((void**)&p_ctxpbf,  g_ctxp_bf16);
    cudaGetSymbolAddress((void**)&p_ctxbf,   g_ctx_bf16);
    cudaGetSymbolAddress((void**)&p_WctxTbf, g_WctxT_bf16);
    cudaGetSymbolAddress((void**)&p_WhidTbf, g_WhidT_bf16);
    cudaGetSymbolAddress((void**)&p_Wihbf,   g_Wih_bf16);
    cudaGetSymbolAddress((void**)&p_Whhbf,   g_Whh_bf16);
    cudaGetSymbolAddress((void**)&p_h2obf,   g_h2o_bf16);
    cudaGetSymbolAddress((void**)&p_octxbf,  g_octx_bf16);
    cudaGetSymbolAddress((void**)&p_Wbf,     g_Wo2p_bf16);
    cudaGetSymbolAddress((void**)&p_pbf,     g_p_bf16);
    cudaGetSymbolAddress((void**)&p_h,       g_h);
    cudaGetSymbolAddress((void**)&p_hqp,     g_hq_part);
    cudaGetSymbolAddress((void**)&p_z,       g_z);
    cudaGetSymbolAddress((void**)&p_gip,     g_gi_part);
    cudaGetSymbolAddress((void**)&p_ghp,     g_gh_part);
    cudaGetSymbolAddress((void**)&p_o1p,     g_o1_part);
    cudaGetSymbolAddress((void**)&p_o2p,     g_o2_part);

    // one-time prep (zero-init folded into k_cvt_all)
    k_cvt_all<<<(unsigned)((CVT_N7 + 255) / 256), 256>>>(ctx, gru_W_ih, gru_W_hh,
                                                         h2o_W, octx_W, o2p_W);
    k_transpose_bf16<<<dim3(32, 32), dim3(32, 8)>>>(att_ctx2ctx, p_WctxTbf, Cdim, Cdim);
    k_transpose_bf16<<<dim3(32, 32), dim3(32, 8)>>>(att_hid2ctx, p_WhidTbf, Hdim, Cdim);
    gemm_bf16_m128<<<dim3(Cdim / 128, (Sdim * Bn) / 128), 256>>>(
        p_ctxbf, p_WctxTbf, p_ctxpbf, Cdim, Cdim);

    for (int t = 0; t < NSTEP; t++) {
        k_att<<<Bn, 256>>>(att_mlp, y, t);
        gemm_bf16_gigh_sk<<<dim3((3 * Hdim) / 64, 2, 4), 256>>>(
            embW, y, t, p_Wihbf, p_gip, p_Whhbf, p_ghp);
        k_gru<<<(Bn * Hdim) / 256, 256>>>(gru_b_ih, gru_b_hh);
        // o1, o2 (this step) + hq (next step) in one launch
        gemm_bf16_m64_tri<<<dim3(Cdim / 64, 3, 4), 256>>>(
            p_h, p_z, p_h2obf, p_octxbf, p_WhidTbf, p_o1p, p_o2p, p_hqp);
        k_pvec<<<(Bn * Edim) / 256, 256>>>(embW, y, h2o_b, octx_b, t);
        gemm_bf16_logits_nll<<<NVBLK, 256>>>(p_pbf, p_Wbf, o2p_b, y, t, Edim);
    }
    k_final<<<1, 256>>>(y, (float*)d_out);
}

// round 15
// speedup vs baseline: 1.3216x; 1.0192x over previous
#include <cuda_runtime.h>
#include <cuda_bf16.h>
#include <math.h>

#define Sdim 196
#define Bn   64
#define Cdim 1024
#define Hdim 1024
#define Edim 512
#define Vdim 32000
#define NSTEP 19
#define NVBLK (Vdim / 256)   // 125 logits blocks

// ---------------- scratch (device globals) -----------------------------------
__device__ __nv_bfloat16 g_ctxp_bf16[(size_t)Sdim * Bn * Cdim];
__device__ __nv_bfloat16 g_ctx_bf16[(size_t)Sdim * Bn * Cdim];
__device__ __nv_bfloat16 g_WctxT_bf16[Cdim * Cdim];
__device__ __nv_bfloat16 g_WhidT_bf16[Hdim * Cdim];
__device__ __nv_bfloat16 g_Wih_bf16[3 * Hdim * (Edim + Cdim)];
__device__ __nv_bfloat16 g_Whh_bf16[3 * Hdim * Hdim];
__device__ __nv_bfloat16 g_h2o_bf16[Edim * Hdim];
__device__ __nv_bfloat16 g_octx_bf16[Edim * Cdim];
__device__ __nv_bfloat16 g_Wo2p_bf16[(size_t)Vdim * Edim];
__device__ __nv_bfloat16 g_p_bf16[Bn * Edim];
__device__ float g_h[Bn * Hdim];
__device__ float g_hq_part[4 * Bn * Cdim];
__device__ float g_z[Bn * Cdim];
__device__ float g_gi_part[4 * Bn * 3 * Hdim];
__device__ float g_gh_part[4 * Bn * 3 * Hdim];
__device__ float g_o1_part[4 * Bn * Edim];
__device__ float g_o2_part[4 * Bn * Edim];
__device__ float g_pm[NVBLK * Bn];
__device__ float g_ps[NVBLK * Bn];
__device__ float g_ltgt[Bn];
__device__ float g_nll[NSTEP * Bn];

// ---------------- fast math ---------------------------------------------------
__device__ __forceinline__ float ftanh(float x) {
    float xc = fminf(fmaxf(x, -15.f), 15.f);
    float e = __expf(2.f * xc);
    return __fdividef(e - 1.f, e + 1.f);
}
__device__ __forceinline__ float ftanh_fast(float x) {
    float y;
    asm("tanh.approx.f32 %0, %1;" : "=f"(y) : "f"(x));
    return y;
}
__device__ __forceinline__ float fsig(float x) {
    return __fdividef(1.f, 1.f + __expf(-x));
}
__device__ __forceinline__ void mma_bf16(float* d, const unsigned* a4, const unsigned* b2) {
    asm volatile(
        "mma.sync.aligned.m16n8k16.row.col.f32.bf16.bf16.f32 "
        "{%0,%1,%2,%3}, {%4,%5,%6,%7}, {%8,%9}, {%0,%1,%2,%3};\n"
        : "+f"(d[0]), "+f"(d[1]), "+f"(d[2]), "+f"(d[3])
        : "r"(a4[0]), "r"(a4[1]), "r"(a4[2]), "r"(a4[3]), "r"(b2[0]), "r"(b2[1]));
}
__device__ __forceinline__ unsigned smem_u32(const void* p) {
    return (unsigned)__cvta_generic_to_shared(p);
}
__device__ __forceinline__ void ldmatrix_x4(unsigned* r, unsigned addr) {
    asm volatile("ldmatrix.sync.aligned.m8n8.x4.shared.b16 {%0,%1,%2,%3}, [%4];"
        : "=r"(r[0]), "=r"(r[1]), "=r"(r[2]), "=r"(r[3]) : "r"(addr));
}
__device__ __forceinline__ void ldmatrix_x2(unsigned* r, unsigned addr) {
    asm volatile("ldmatrix.sync.aligned.m8n8.x2.shared.b16 {%0,%1}, [%2];"
        : "=r"(r[0]), "=r"(r[1]) : "r"(addr));
}
__device__ __forceinline__ void lse_upd(float& m, float& s, float v) {
    if (v > m) { s = s * __expf(m - v) + 1.f; m = v; }
    else       { s += __expf(v - m); }
}
__device__ __forceinline__ void lse_comb(float& m, float& s, float m2, float s2) {
    float M = fmaxf(m, m2);
    s = s * __expf(m - M) + s2 * __expf(m2 - M);
    m = M;
}

// ---------------- block reductions (fixed order) ------------------------------
__device__ __forceinline__ float blockReduceSum(float v, float* red) {
    #pragma unroll
    for (int o = 16; o; o >>= 1) v += __shfl_xor_sync(0xffffffffu, v, o);
    if ((threadIdx.x & 31) == 0) red[threadIdx.x >> 5] = v;
    __syncthreads();
    float t = 0.f;
    int nw = blockDim.x >> 5;
    for (int i = 0; i < nw; i++) t += red[i];
    __syncthreads();
    return t;
}
__device__ __forceinline__ float blockReduceMax(float v, float* red) {
    #pragma unroll
    for (int o = 16; o; o >>= 1) v = fmaxf(v, __shfl_xor_sync(0xffffffffu, v, o));
    if ((threadIdx.x & 31) == 0) red[threadIdx.x >> 5] = v;
    __syncthreads();
    float t = red[0];
    int nw = blockDim.x >> 5;
    for (int i = 1; i < nw; i++) t = fmaxf(t, red[i]);
    __syncthreads();
    return t;
}

// ---------------- one-time prep kernels ---------------------------------------
__global__ void k_transpose_bf16(const float* __restrict__ in, __nv_bfloat16* __restrict__ out, int R, int Ccols) {
    __shared__ float t[32][33];
    int c0 = blockIdx.x * 32, r0 = blockIdx.y * 32;
    #pragma unroll
    for (int i = 0; i < 4; i++)
        t[threadIdx.y + i * 8][threadIdx.x] = in[(size_t)(r0 + threadIdx.y + i * 8) * Ccols + c0 + threadIdx.x];
    __syncthreads();
    #pragma unroll
    for (int i = 0; i < 4; i++)
        out[(size_t)(c0 + threadIdx.y + i * 8) * R + r0 + threadIdx.x] =
            __float2bfloat16_rn(t[threadIdx.x][threadIdx.y + i * 8]);
}

// all plain fp32->bf16 conversions + zero-init in one launch (float4 index)
#define CVT_N0 ((size_t)Sdim * Bn * Cdim / 4)
#define CVT_N1 (CVT_N0 + (size_t)3 * Hdim * (Edim + Cdim) / 4)
#define CVT_N2 (CVT_N1 + (size_t)3 * Hdim * Hdim / 4)
#define CVT_N3 (CVT_N2 + (size_t)Edim * Hdim / 4)
#define CVT_N4 (CVT_N3 + (size_t)Edim * Cdim / 4)
#define CVT_N5 (CVT_N4 + (size_t)Vdim * Edim / 4)
#define CVT_N6 (CVT_N5 + (size_t)(Bn * Hdim) / 4)        // zero g_h
#define CVT_N7 (CVT_N6 + (size_t)(4 * Bn * Cdim) / 4)    // zero g_hq_part
__global__ void k_cvt_all(const float* __restrict__ ctx, const float* __restrict__ Wih,
                          const float* __restrict__ Whh, const float* __restrict__ h2o,
                          const float* __restrict__ octx, const float* __restrict__ o2p) {
    size_t i = (size_t)blockIdx.x * 256 + threadIdx.x;   // float4 index
    if (i >= CVT_N7) return;
    if (i >= CVT_N5) {
        float4 zz = make_float4(0.f, 0.f, 0.f, 0.f);
        if (i < CVT_N6) *(float4*)&g_h[(i - CVT_N5) * 4] = zz;
        else            *(float4*)&g_hq_part[(i - CVT_N6) * 4] = zz;
        return;
    }
    const float* src; __nv_bfloat16* dst; size_t off;
    if      (i < CVT_N0) { src = ctx;  dst = g_ctx_bf16;  off = i; }
    else if (i < CVT_N1) { src = Wih;  dst = g_Wih_bf16;  off = i - CVT_N0; }
    else if (i < CVT_N2) { src = Whh;  dst = g_Whh_bf16;  off = i - CVT_N1; }
    else if (i < CVT_N3) { src = h2o;  dst = g_h2o_bf16;  off = i - CVT_N2; }
    else if (i < CVT_N4) { src = octx; dst = g_octx_bf16; off = i - CVT_N3; }
    else                 { src = o2p;  dst = g_Wo2p_bf16; off = i - CVT_N4; }
    float4 v = *(const float4*)&src[off * 4];
    __nv_bfloat162* o = (__nv_bfloat162*)&dst[off * 4];
    o[0] = __floats2bfloat162_rn(v.x, v.y);
    o[1] = __floats2bfloat162_rn(v.z, v.w);
}

// ============ BF16 NT GEMM, 128x128 tile, bf16 out, pipelined + ldmatrix ======
__global__ __launch_bounds__(256) void gemm_bf16_m128(
    const __nv_bfloat16* __restrict__ A, const __nv_bfloat16* __restrict__ B,
    __nv_bfloat16* __restrict__ C, int N, int K) {
    __shared__ __nv_bfloat16 As[128][72];
    __shared__ __nv_bfloat16 Bs[128][72];
    const int row0 = blockIdx.y * 128, col0 = blockIdx.x * 128;
    const int tid = threadIdx.x;
    const int wid = tid >> 5, lane = tid & 31;
    const int gID = lane >> 2, tig = lane & 3;
    const int m0w = (wid >> 2) * 64, n0w = (wid & 3) * 32;
    const int lrow = tid >> 1, lcol = (tid & 1) * 32;
    const int lmr = ((lane >> 3) & 1) * 8 + (lane & 7);   // A/B row-in-tile
    const int lmcA = ((lane >> 4) & 1) * 8;               // A col-sel
    const int lmrB = ((lane >> 4) & 1) * 8 + (lane & 7);  // B row-in-group-pair
    const int lmcB = ((lane >> 3) & 1) * 8;               // B col-sel
    float acc[4][4][4] = {};
    uint4 ra[4], rb[4];
    #pragma unroll
    for (int i = 0; i < 4; i++) {
        ra[i] = *(const uint4*)&A[(size_t)(row0 + lrow) * K + lcol + i * 8];
        rb[i] = *(const uint4*)&B[(size_t)(col0 + lrow) * K + lcol + i * 8];
    }
    for (int k0 = 0; k0 < K; k0 += 64) {
        #pragma unroll
        for (int i = 0; i < 4; i++) {
            *(uint4*)&As[lrow][lcol + i * 8] = ra[i];
            *(uint4*)&Bs[lrow][lcol + i * 8] = rb[i];
        }
        __syncthreads();
        if (k0 + 64 < K) {
            #pragma unroll
            for (int i = 0; i < 4; i++) {
                ra[i] = *(const uint4*)&A[(size_t)(row0 + lrow) * K + k0 + 64 + lcol + i * 8];
                rb[i] = *(const uint4*)&B[(size_t)(col0 + lrow) * K + k0 + 64 + lcol + i * 8];
            }
        }
        #pragma unroll
        for (int kk = 0; kk < 4; kk++) {
            const int kb = kk * 16;
            unsigned af[4][4], bf[4][2];
            #pragma unroll
            for (int mi = 0; mi < 4; mi++)
                ldmatrix_x4(af[mi], smem_u32(&As[m0w + mi * 16 + lmr][kb + lmcA]));
            #pragma unroll
            for (int nj = 0; nj < 2; nj++) {
                unsigned tmp[4];
                ldmatrix_x4(tmp, smem_u32(&Bs[n0w + nj * 16 + lmrB][kb + lmcB]));
                bf[nj * 2][0] = tmp[0]; bf[nj * 2][1] = tmp[1];
                bf[nj * 2 + 1][0] = tmp[2]; bf[nj * 2 + 1][1] = tmp[3];
            }
            #pragma unroll
            for (int mi = 0; mi < 4; mi++)
                #pragma unroll
                for (int ni = 0; ni < 4; ni++)
                    mma_bf16(acc[mi][ni], af[mi], bf[ni]);
        }
        __syncthreads();
    }
    #pragma unroll
    for (int mi = 0; mi < 4; mi++)
        #pragma unroll
        for (int ni = 0; ni < 4; ni++) {
            int r = row0 + m0w + mi * 16 + gID;
            int c = col0 + n0w + ni * 8 + tig * 2;
            *(__nv_bfloat162*)&C[(size_t)r * N + c]       = __floats2bfloat162_rn(acc[mi][ni][0], acc[mi][ni][1]);
            *(__nv_bfloat162*)&C[(size_t)(r + 8) * N + c] = __floats2bfloat162_rn(acc[mi][ni][2], acc[mi][ni][3]);
        }
}

// ============ BF16 triple GEMM (o1, o2, hq-next), M=64, split-K, ldmatrix =====
__global__ __launch_bounds__(256) void gemm_bf16_m64_tri(
    const float* __restrict__ h, const float* __restrict__ z,
    const __nv_bfloat16* __restrict__ Bh2o, const __nv_bfloat16* __restrict__ Boctx,
    const __nv_bfloat16* __restrict__ Bhid,
    float* __restrict__ Co1, float* __restrict__ Co2, float* __restrict__ Chq) {
    const int prob = blockIdx.y;
    const float* A; const __nv_bfloat16* B; float* C; int N;
    if (prob == 0)      { A = h; B = Bh2o;  C = Co1; N = Edim; }
    else if (prob == 1) { A = z; B = Boctx; C = Co2; N = Edim; }
    else                { A = h; B = Bhid;  C = Chq; N = Cdim; }
    const int col0 = blockIdx.x * 64;
    if (col0 >= N) return;
    const int K = Hdim, kChunk = Hdim / 4;
    __shared__ __nv_bfloat16 As[64][72];
    __shared__ __nv_bfloat16 Bs[64][72];
    const int kbase = blockIdx.z * kChunk;
    const int tid = threadIdx.x;
    const int wid = tid >> 5, lane = tid & 31;
    const int gID = lane >> 2, tig = lane & 3;
    const int lrow = tid >> 2, lseg = (tid & 3) * 16;
    const int lmr = ((lane >> 3) & 1) * 8 + (lane & 7);
    const int lmcA = ((lane >> 4) & 1) * 8;
    const int lmrB2 = lane & 7;                 // x2: lanes 0-15 matter
    const int lmcB2 = ((lane >> 3) & 1) * 8;
    float acc[4][4] = {};
    for (int kt = 0; kt < kChunk; kt += 64) {
        const int k0 = kbase + kt;
        #pragma unroll
        for (int i = 0; i < 4; i++) {
            float4 a = *(const float4*)&A[(size_t)lrow * K + k0 + lseg + i * 4];
            __nv_bfloat162* d = (__nv_bfloat162*)&As[lrow][lseg + i * 4];
            d[0] = __floats2bfloat162_rn(a.x, a.y);
            d[1] = __floats2bfloat162_rn(a.z, a.w);
        }
        *(uint4*)&Bs[lrow][lseg]     = *(const uint4*)&B[(size_t)(col0 + lrow) * K + k0 + lseg];
        *(uint4*)&Bs[lrow][lseg + 8] = *(const uint4*)&B[(size_t)(col0 + lrow) * K + k0 + lseg + 8];
        __syncthreads();
        #pragma unroll
        for (int kk = 0; kk < 4; kk++) {
            const int kb = kk * 16;
            unsigned bfv[2];
            ldmatrix_x2(bfv, smem_u32(&Bs[wid * 8 + lmrB2][kb + lmcB2]));
            #pragma unroll
            for (int mi = 0; mi < 4; mi++) {
                unsigned af[4];
                ldmatrix_x4(af, smem_u32(&As[mi * 16 + lmr][kb + lmcA]));
                mma_bf16(acc[mi], af, bfv);
            }
        }
        __syncthreads();
    }
    float* Cp = C + (size_t)blockIdx.z * 64 * N;
    #pragma unroll
    for (int mi = 0; mi < 4; mi++) {
        int r = mi * 16 + gID;
        int c = col0 + wid * 8 + tig * 2;
        *(float2*)&Cp[(size_t)r * N + c]       = make_float2(acc[mi][0], acc[mi][1]);
        *(float2*)&Cp[(size_t)(r + 8) * N + c] = make_float2(acc[mi][2], acc[mi][3]);
    }
}

// ============ merged GRU GEMMs (bf16, ldmatrix): y=0 -> gi, y=1 -> gh =========
__global__ __launch_bounds__(256) void gemm_bf16_gigh_sk(
    const float* __restrict__ embW, const int* __restrict__ y, int t,
    const __nv_bfloat16* __restrict__ Wih, float* __restrict__ Cgi,
    const __nv_bfloat16* __restrict__ Whh, float* __restrict__ Cgh) {
    const bool is_gi = (blockIdx.y == 0);
    const int K      = is_gi ? (Edim + Cdim) : Hdim;
    const int kChunk = is_gi ? ((Edim + Cdim) / 4) : (Hdim / 4);
    const __nv_bfloat16* B = is_gi ? Wih : Whh;
    float* C = is_gi ? Cgi : Cgh;
    const int N = 3 * Hdim;
    __shared__ __nv_bfloat16 As[64][72];
    __shared__ __nv_bfloat16 Bs[64][72];
    const int col0 = blockIdx.x * 64;
    const int kbase = blockIdx.z * kChunk;
    const int tid = threadIdx.x;
    const int wid = tid >> 5, lane = tid & 31;
    const int gID = lane >> 2, tig = lane & 3;
    const int lrow = tid >> 2, lseg = (tid & 3) * 16;
    const int lmr = ((lane >> 3) & 1) * 8 + (lane & 7);
    const int lmcA = ((lane >> 4) & 1) * 8;
    const int lmrB2 = lane & 7;
    const int lmcB2 = ((lane >> 3) & 1) * 8;
    const int yid = is_gi ? y[t * Bn + lrow] : 0;
    float acc[4][4] = {};
    for (int kt = 0; kt < kChunk; kt += 64) {
        const int k0 = kbase + kt;
        const float* Arow;
        if (is_gi) Arow = (k0 < Edim) ? &embW[(size_t)yid * Edim + k0]
                                      : &g_z[lrow * Cdim + (k0 - Edim)];
        else       Arow = &g_h[lrow * Hdim + k0];
        #pragma unroll
        for (int i = 0; i < 4; i++) {
            float4 a = *(const float4*)&Arow[lseg + i * 4];
            __nv_bfloat162* d = (__nv_bfloat162*)&As[lrow][lseg + i * 4];
            d[0] = __floats2bfloat162_rn(a.x, a.y);
            d[1] = __floats2bfloat162_rn(a.z, a.w);
        }
        *(uint4*)&Bs[lrow][lseg]     = *(const uint4*)&B[(size_t)(col0 + lrow) * K + k0 + lseg];
        *(uint4*)&Bs[lrow][lseg + 8] = *(const uint4*)&B[(size_t)(col0 + lrow) * K + k0 + lseg + 8];
        __syncthreads();
        #pragma unroll
        for (int kk = 0; kk < 4; kk++) {
            const int kb = kk * 16;
            unsigned bfv[2];
            ldmatrix_x2(bfv, smem_u32(&Bs[wid * 8 + lmrB2][kb + lmcB2]));
            #pragma unroll
            for (int mi = 0; mi < 4; mi++) {
                unsigned af[4];
                ldmatrix_x4(af, smem_u32(&As[mi * 16 + lmr][kb + lmcA]));
                mma_bf16(acc[mi], af, bfv);
            }
        }
        __syncthreads();
    }
    float* Cp = C + (size_t)blockIdx.z * 64 * N;
    #pragma unroll
    for (int mi = 0; mi < 4; mi++) {
        int r = mi * 16 + gID;
        int c = col0 + wid * 8 + tig * 2;
        *(float2*)&Cp[(size_t)r * N + c]       = make_float2(acc[mi][0], acc[mi][1]);
        *(float2*)&Cp[(size_t)(r + 8) * N + c] = make_float2(acc[mi][2], acc[mi][3]);
    }
}

// ============ BF16 logits GEMM + fused partial NLL (ldmatrix) =================
__global__ __launch_bounds__(256) void gemm_bf16_logits_nll(
    const __nv_bfloat16* __restrict__ A, const __nv_bfloat16* __restrict__ B,
    const float* __restrict__ bias, const int* __restrict__ y, int t, int K) {
    __shared__ __align__(16) unsigned char sbuf[9216 + 36864];
    __nv_bfloat16 (*As)[72] = reinterpret_cast<__nv_bfloat16(*)[72]>(sbuf);
    __nv_bfloat16 (*Bs)[72] = reinterpret_cast<__nv_bfloat16(*)[72]>(sbuf + 9216);
    float (*sm)[8] = reinterpret_cast<float(*)[8]>(sbuf);           // overlays As
    float (*ss)[8] = reinterpret_cast<float(*)[8]>(sbuf + 2048);    // overlays As
    const int col0 = blockIdx.x * 256;
    const int tid = threadIdx.x;
    const int wid = tid >> 5, lane = tid & 31;
    const int gID = lane >> 2, tig = lane & 3;
    const int n0w = wid * 32;
    const int lmr = ((lane >> 3) & 1) * 8 + (lane & 7);
    const int lmcA = ((lane >> 4) & 1) * 8;
    const int lmrB = ((lane >> 4) & 1) * 8 + (lane & 7);
    const int lmcB = ((lane >> 3) & 1) * 8;
    float acc[4][4][4] = {};
    for (int k0 = 0; k0 < K; k0 += 64) {
        {
            int ar = tid >> 2, as = (tid & 3) * 16;
            *(uint4*)&As[ar][as]     = *(const uint4*)&A[(size_t)ar * K + k0 + as];
            *(uint4*)&As[ar][as + 8] = *(const uint4*)&A[(size_t)ar * K + k0 + as + 8];
            #pragma unroll
            for (int i = 0; i < 8; i++)
                *(uint4*)&Bs[tid][i * 8] = *(const uint4*)&B[(size_t)(col0 + tid) * K + k0 + i * 8];
        }
        __syncthreads();
        #pragma unroll
        for (int kk = 0; kk < 4; kk++) {
            const int kb = kk * 16;
            unsigned af[4][4], bf[4][2];
            #pragma unroll
            for (int mi = 0; mi < 4; mi++)
                ldmatrix_x4(af[mi], smem_u32(&As[mi * 16 + lmr][kb + lmcA]));
            #pragma unroll
            for (int nj = 0; nj < 2; nj++) {
                unsigned tmp[4];
                ldmatrix_x4(tmp, smem_u32(&Bs[n0w + nj * 16 + lmrB][kb + lmcB]));
                bf[nj * 2][0] = tmp[0]; bf[nj * 2][1] = tmp[1];
                bf[nj * 2 + 1][0] = tmp[2]; bf[nj * 2 + 1][1] = tmp[3];
            }
            #pragma unroll
            for (int mi = 0; mi < 4; mi++)
                #pragma unroll
                for (int ni = 0; ni < 4; ni++)
                    mma_bf16(acc[mi][ni], af[mi], bf[ni]);
        }
        __syncthreads();
    }
    #pragma unroll
    for (int mi = 0; mi < 4; mi++) {
        const int r  = mi * 16 + gID;
        const int r2 = r + 8;
        const int tgt  = y[(t + 1) * Bn + r];
        const int tgt2 = y[(t + 1) * Bn + r2];
        float m1 = -1e30f, s1 = 0.f, m2 = -1e30f, s2 = 0.f;
        #pragma unroll
        for (int ni = 0; ni < 4; ni++) {
            int c = col0 + n0w + ni * 8 + tig * 2;
            float b0 = bias[c], b1 = bias[c + 1];
            float v0 = acc[mi][ni][0] + b0, v1 = acc[mi][ni][1] + b1;
            float v2 = acc[mi][ni][2] + b0, v3 = acc[mi][ni][3] + b1;
            if (c == tgt)      g_ltgt[r]  = v0;
            if (c + 1 == tgt)  g_ltgt[r]  = v1;
            if (c == tgt2)     g_ltgt[r2] = v2;
            if (c + 1 == tgt2) g_ltgt[r2] = v3;
            lse_upd(m1, s1, v0); lse_upd(m1, s1, v1);
            lse_upd(m2, s2, v2); lse_upd(m2, s2, v3);
        }
        #pragma unroll
        for (int off = 1; off <= 2; off <<= 1) {
            float om = __shfl_xor_sync(0xffffffffu, m1, off);
            float os = __shfl_xor_sync(0xffffffffu, s1, off);
            lse_comb(m1, s1, om, os);
            om = __shfl_xor_sync(0xffffffffu, m2, off);
            os = __shfl_xor_sync(0xffffffffu, s2, off);
            lse_comb(m2, s2, om, os);
        }
        if (tig == 0) {
            sm[r][wid] = m1; ss[r][wid] = s1;
            sm[r2][wid] = m2; ss[r2][wid] = s2;
        }
    }
    __syncthreads();
    if (tid < 64) {
        float M = sm[tid][0], S = ss[tid][0];
        #pragma unroll
        for (int w = 1; w < 8; w++) lse_comb(M, S, sm[tid][w], ss[tid][w]);
        g_pm[blockIdx.x * Bn + tid] = M;
        g_ps[blockIdx.x * Bn + tid] = S;
    }
}

// ============ fused attention + previous step's NLL finalize ==================
__global__ __launch_bounds__(256) void k_att(const float* __restrict__ mlp,
                                             const int* __restrict__ y, int t) {
    const int b = blockIdx.x;
    const int tid = threadIdx.x;
    const int wid = tid >> 5, lane = tid & 31;
    __shared__ float sc[200];
    __shared__ float red[8];
    if (t > 0 && wid == 7) {
        float m = -1e30f, s = 0.f;
        for (int i = lane; i < NVBLK; i += 32)
            lse_comb(m, s, g_pm[i * Bn + b], g_ps[i * Bn + b]);
        #pragma unroll
        for (int off = 16; off; off >>= 1) {
            float om = __shfl_xor_sync(0xffffffffu, m, off);
            float os = __shfl_xor_sync(0xffffffffu, s, off);
            lse_comb(m, s, om, os);
        }
        if (lane == 0) {
            int tgt = y[t * Bn + b];
            g_nll[(t - 1) * Bn + b] = (tgt != 0) ? (m + logf(s) - g_ltgt[b]) : 0.f;
        }
    }
    float hqv[32], mlpv[32];
    #pragma unroll
    for (int j = 0; j < 4; j++) {
        #pragma unroll
        for (int u = 0; u < 8; u++) {
            int m = lane * 8 + j * 256 + u;
            float v = g_hq_part[b * Cdim + m]
                    + g_hq_part[(Bn + b) * Cdim + m]
                    + g_hq_part[(2 * Bn + b) * Cdim + m]
                    + g_hq_part[(3 * Bn + b) * Cdim + m];
            hqv[j * 8 + u] = v;
            mlpv[j * 8 + u] = mlp[m];
        }
    }
    for (int s = wid; s < Sdim; s += 8) {
        const __nv_bfloat16* row = g_ctxp_bf16 + ((size_t)s * Bn + b) * Cdim;
        float sum = 0.f;
        #pragma unroll
        for (int j = 0; j < 4; j++) {
            int m = lane * 8 + j * 256;
            uint4 u = *(const uint4*)&row[m];
            float2 f0 = __bfloat1622float2(*(__nv_bfloat162*)&u.x);
            float2 f1 = __bfloat1622float2(*(__nv_bfloat162*)&u.y);
            float2 f2 = __bfloat1622float2(*(__nv_bfloat162*)&u.z);
            float2 f3 = __bfloat1622float2(*(__nv_bfloat162*)&u.w);
            sum += ftanh_fast(f0.x + hqv[j * 8 + 0]) * mlpv[j * 8 + 0];
            sum += ftanh_fast(f0.y + hqv[j * 8 + 1]) * mlpv[j * 8 + 1];
            sum += ftanh_fast(f1.x + hqv[j * 8 + 2]) * mlpv[j * 8 + 2];
            sum += ftanh_fast(f1.y + hqv[j * 8 + 3]) * mlpv[j * 8 + 3];
            sum += ftanh_fast(f2.x + hqv[j * 8 + 4]) * mlpv[j * 8 + 4];
            sum += ftanh_fast(f2.y + hqv[j * 8 + 5]) * mlpv[j * 8 + 5];
            sum += ftanh_fast(f3.x + hqv[j * 8 + 6]) * mlpv[j * 8 + 6];
            sum += ftanh_fast(f3.y + hqv[j * 8 + 7]) * mlpv[j * 8 + 7];
        }
        #pragma unroll
        for (int o = 16; o; o >>= 1) sum += __shfl_xor_sync(0xffffffffu, sum, o);
        if (lane == 0) sc[s] = sum;
    }
    __syncthreads();
    float v = (tid < Sdim) ? sc[tid] : -1e30f;
    float mx = blockReduceMax(v, red);
    float e = (tid < Sdim) ? __expf(v - mx) : 0.f;
    float tot = blockReduceSum(e, red);
    if (tid < Sdim) sc[tid] = __fdividef(e, tot);
    __syncthreads();
    const int c4 = tid * 4;
    float4 acc = make_float4(0.f, 0.f, 0.f, 0.f);
    #pragma unroll 4
    for (int s = 0; s < Sdim; s++) {
        float a = sc[s];
        uint2 u = *(const uint2*)&g_ctx_bf16[((size_t)s * Bn + b) * Cdim + c4];
        float2 f0 = __bfloat1622float2(*(__nv_bfloat162*)&u.x);
        float2 f1 = __bfloat1622float2(*(__nv_bfloat162*)&u.y);
        acc.x = fmaf(a, f0.x, acc.x); acc.y = fmaf(a, f0.y, acc.y);
        acc.z = fmaf(a, f1.x, acc.z); acc.w = fmaf(a, f1.y, acc.w);
    }
    *(float4*)&g_z[b * Cdim + c4] = acc;
}

// ---------------- per-step elementwise kernels --------------------------------
__global__ void k_gru(const float* __restrict__ b_ih, const float* __restrict__ b_hh) {
    const int i = blockIdx.x * 256 + threadIdx.x;
    const int b = i >> 10, j = i & (Hdim - 1);
    float ir = b_ih[j], iz = b_ih[Hdim + j], in_ = b_ih[2 * Hdim + j];
    #pragma unroll
    for (int p = 0; p < 4; p++) {
        const float* g = g_gi_part + ((size_t)p * Bn + b) * 3 * Hdim;
        ir += g[j]; iz += g[Hdim + j]; in_ += g[2 * Hdim + j];
    }
    float hr = b_hh[j], hz = b_hh[Hdim + j], hn = b_hh[2 * Hdim + j];
    #pragma unroll
    for (int p = 0; p < 4; p++) {
        const float* g = g_gh_part + ((size_t)p * Bn + b) * 3 * Hdim;
        hr += g[j]; hz += g[Hdim + j]; hn += g[2 * Hdim + j];
    }
    float r = fsig(ir + hr);
    float zz = fsig(iz + hz);
    float n = ftanh(in_ + r * hn);
    float hold = g_h[i];
    g_h[i] = (1.f - zz) * n + zz * hold;
}

__global__ void k_pvec(const float* __restrict__ embW, const int* __restrict__ y,
                       const float* __restrict__ h2o_b, const float* __restrict__ octx_b, int t) {
    const int i = blockIdx.x * 256 + threadIdx.x;
    const int b = i >> 9, e = i & (Edim - 1);
    float o1 = h2o_b[e], o2 = octx_b[e];
    #pragma unroll
    for (int p = 0; p < 4; p++) {
        o1 += g_o1_part[p * Bn * Edim + i];
        o2 += g_o2_part[p * Bn * Edim + i];
    }
    float l = ftanh(o1);
    l += embW[(size_t)y[t * Bn + b] * Edim + e];
    l += o2;
    g_p_bf16[i] = __float2bfloat16_rn(ftanh(l));
}

// final: last step's NLL from partials + total sum
__global__ __launch_bounds__(256) void k_final(const int* __restrict__ y, float* __restrict__ out) {
    __shared__ float red[8];
    const int tid = threadIdx.x;
    if (tid < Bn) {
        float m = -1e30f, s = 0.f;
        for (int i = 0; i < NVBLK; i++)
            lse_comb(m, s, g_pm[i * Bn + tid], g_ps[i * Bn + tid]);
        int tgt = y[NSTEP * Bn + tid];
        g_nll[(NSTEP - 1) * Bn + tid] = (tgt != 0) ? (m + logf(s) - g_ltgt[tid]) : 0.f;
    }
    __syncthreads();
    float s = 0.f;
    for (int i = tid; i < NSTEP * Bn; i += 256) s += g_nll[i];
    float tot = blockReduceSum(s, red);
    if (tid == 0) out[0] = tot;
}

// ---------------- launch ------------------------------------------------------
extern "C" void kernel_launch(void* const* d_in, const int* in_sizes, int n_in,
                              void* d_out, int out_size) {
    const float* ctx         = (const float*)d_in[0];
    const int*   y           = (const int*)  d_in[1];
    const float* embW        = (const float*)d_in[2];
    const float* att_ctx2ctx = (const float*)d_in[3];
    const float* att_hid2ctx = (const float*)d_in[4];
    const float* att_mlp     = (const float*)d_in[5];
    const float* gru_W_ih    = (const float*)d_in[6];
    const float* gru_b_ih    = (const float*)d_in[7];
    const float* gru_W_hh    = (const float*)d_in[8];
    const float* gru_b_hh    = (const float*)d_in[9];
    const float* h2o_W       = (const float*)d_in[10];
    const float* h2o_b       = (const float*)d_in[11];
    const float* octx_W      = (const float*)d_in[12];
    const float* octx_b      = (const float*)d_in[13];
    const float* o2p_W       = (const float*)d_in[14];
    const float* o2p_b       = (const float*)d_in[15];

    float *p_h, *p_hqp, *p_z, *p_gip, *p_ghp, *p_o1p, *p_o2p;
    __nv_bfloat16 *p_ctxpbf, *p_ctxbf, *p_WctxTbf, *p_WhidTbf, *p_Wihbf, *p_Whhbf,
                  *p_h2obf, *p_octxbf, *p_Wbf, *p_pbf;
    cudaGetSymbolAddress((void**)&p_ctxpbf,  g_ctxp_bf16);
    cudaGetSymbolAddress((void**)&p_ctxbf,   g_ctx_bf16);
    cudaGetSymbolAddress((void**)&p_WctxTbf, g_WctxT_bf16);
    cudaGetSymbolAddress((void**)&p_WhidTbf, g_WhidT_bf16);
    cudaGetSymbolAddress((void**)&p_Wihbf,   g_Wih_bf16);
    cudaGetSymbolAddress((void**)&p_Whhbf,   g_Whh_bf16);
    cudaGetSymbolAddress((void**)&p_h2obf,   g_h2o_bf16);
    cudaGetSymbolAddress((void**)&p_octxbf,  g_octx_bf16);
    cudaGetSymbolAddress((void**)&p_Wbf,     g_Wo2p_bf16);
    cudaGetSymbolAddress((void**)&p_pbf,     g_p_bf16);
    cudaGetSymbolAddress((void**)&p_h,       g_h);
    cudaGetSymbolAddress((void**)&p_hqp,     g_hq_part);
    cudaGetSymbolAddress((void**)&p_z,       g_z);
    cudaGetSymbolAddress((void**)&p_gip,     g_gi_part);
    cudaGetSymbolAddress((void**)&p_ghp,     g_gh_part);
    cudaGetSymbolAddress((void**)&p_o1p,     g_o1_part);
    cudaGetSymbolAddress((void**)&p_o2p,     g_o2_part);

    // one-time prep (zero-init folded into k_cvt_all)
    k_cvt_all<<<(unsigned)((CVT_N7 + 255) / 256), 256>>>(ctx, gru_W_ih, gru_W_hh,
                                                         h2o_W, octx_W, o2p_W);
    k_transpose_bf16<<<dim3(32, 32), dim3(32, 8)>>>(att_ctx2ctx, p_WctxTbf, Cdim, Cdim);
    k_transpose_bf16<<<dim3(32, 32), dim3(32, 8)>>>(att_hid2ctx, p_WhidTbf, Hdim, Cdim);
    gemm_bf16_m128<<<dim3(Cdim / 128, (Sdim * Bn) / 128), 256>>>(
        p_ctxbf, p_WctxTbf, p_ctxpbf, Cdim, Cdim);

    for (int t = 0; t < NSTEP; t++) {
        k_att<<<Bn, 256>>>(att_mlp, y, t);
        gemm_bf16_gigh_sk<<<dim3((3 * Hdim) / 64, 2, 4), 256>>>(
            embW, y, t, p_Wihbf, p_gip, p_Whhbf, p_ghp);
        k_gru<<<(Bn * Hdim) / 256, 256>>>(gru_b_ih, gru_b_hh);
        // o1, o2 (this step) + hq (next step) in one launch
        gemm_bf16_m64_tri<<<dim3(Cdim / 64, 3, 4), 256>>>(
            p_h, p_z, p_h2obf, p_octxbf, p_WhidTbf, p_o1p, p_o2p, p_hqp);
        k_pvec<<<(Bn * Edim) / 256, 256>>>(embW, y, h2o_b, octx_b, t);
        gemm_bf16_logits_nll<<<NVBLK, 256>>>(p_pbf, p_Wbf, o2p_b, y, t, Edim);
    }
    k_final<<<1, 256>>>(y, (float*)d_out);
}

// round 17
// speedup vs baseline: 1.3579x; 1.0275x over previous
#include <cuda_runtime.h>
#include <cuda_bf16.h>
#include <math.h>

#define Sdim 196
#define Bn   64
#define Cdim 1024
#define Hdim 1024
#define Edim 512
#define Vdim 32000
#define NSTEP 19
#define NVBLK (Vdim / 256)   // 125 logits blocks

// ---------------- scratch (device globals) -----------------------------------
__device__ __nv_bfloat16 g_ctxp_bf16[(size_t)Sdim * Bn * Cdim];
__device__ __nv_bfloat16 g_ctx_bf16[(size_t)Sdim * Bn * Cdim];
__device__ __nv_bfloat16 g_WctxT_bf16[Cdim * Cdim];
__device__ __nv_bfloat16 g_WhidT_bf16[Hdim * Cdim];
__device__ __nv_bfloat16 g_Wih_bf16[3 * Hdim * (Edim + Cdim)];
__device__ __nv_bfloat16 g_Whh_bf16[3 * Hdim * Hdim];
__device__ __nv_bfloat16 g_h2o_bf16[Edim * Hdim];
__device__ __nv_bfloat16 g_octx_bf16[Edim * Cdim];
__device__ __nv_bfloat16 g_Wo2p_bf16[(size_t)Vdim * Edim];
__device__ __nv_bfloat16 g_p_bf16[Bn * Edim];
__device__ float g_h[Bn * Hdim];
__device__ float g_hq_part[4 * Bn * Cdim];
__device__ float g_z[Bn * Cdim];
__device__ float g_gi_part[4 * Bn * 3 * Hdim];
__device__ float g_gh_part[4 * Bn * 3 * Hdim];
__device__ float g_o1_part[4 * Bn * Edim];
__device__ float g_o2_part[4 * Bn * Edim];
__device__ float g_pm[NVBLK * Bn];
__device__ float g_ps[NVBLK * Bn];
__device__ float g_ltgt[Bn];
__device__ float g_nll[NSTEP * Bn];

// ---------------- fast math / intrinsics --------------------------------------
__device__ __forceinline__ float ftanh(float x) {
    float xc = fminf(fmaxf(x, -15.f), 15.f);
    float e = __expf(2.f * xc);
    return __fdividef(e - 1.f, e + 1.f);
}
__device__ __forceinline__ float ftanh_fast(float x) {
    float y;
    asm("tanh.approx.f32 %0, %1;" : "=f"(y) : "f"(x));
    return y;
}
__device__ __forceinline__ float fsig(float x) {
    return __fdividef(1.f, 1.f + __expf(-x));
}
__device__ __forceinline__ void mma_bf16(float* d, const unsigned* a4, const unsigned* b2) {
    asm volatile(
        "mma.sync.aligned.m16n8k16.row.col.f32.bf16.bf16.f32 "
        "{%0,%1,%2,%3}, {%4,%5,%6,%7}, {%8,%9}, {%0,%1,%2,%3};\n"
        : "+f"(d[0]), "+f"(d[1]), "+f"(d[2]), "+f"(d[3])
        : "r"(a4[0]), "r"(a4[1]), "r"(a4[2]), "r"(a4[3]), "r"(b2[0]), "r"(b2[1]));
}
__device__ __forceinline__ unsigned smem_u32(const void* p) {
    return (unsigned)__cvta_generic_to_shared(p);
}
__device__ __forceinline__ void ldmatrix_x4(unsigned* r, unsigned addr) {
    asm volatile("ldmatrix.sync.aligned.m8n8.x4.shared.b16 {%0,%1,%2,%3}, [%4];"
        : "=r"(r[0]), "=r"(r[1]), "=r"(r[2]), "=r"(r[3]) : "r"(addr));
}
__device__ __forceinline__ void ldmatrix_x2(unsigned* r, unsigned addr) {
    asm volatile("ldmatrix.sync.aligned.m8n8.x2.shared.b16 {%0,%1}, [%2];"
        : "=r"(r[0]), "=r"(r[1]) : "r"(addr));
}
__device__ __forceinline__ void cpa16(unsigned saddr, const void* g) {
    asm volatile("cp.async.cg.shared.global [%0], [%1], 16;" :: "r"(saddr), "l"(g));
}
__device__ __forceinline__ void cpa_commit() { asm volatile("cp.async.commit_group;"); }
__device__ __forceinline__ void cpa_wait1()  { asm volatile("cp.async.wait_group 1;"); }
__device__ __forceinline__ void cpa_wait0()  { asm volatile("cp.async.wait_group 0;"); }
__device__ __forceinline__ void lse_upd(float& m, float& s, float v) {
    if (v > m) { s = s * __expf(m - v) + 1.f; m = v; }
    else       { s += __expf(v - m); }
}
__device__ __forceinline__ void lse_comb(float& m, float& s, float m2, float s2) {
    float M = fmaxf(m, m2);
    s = s * __expf(m - M) + s2 * __expf(m2 - M);
    m = M;
}

// ---------------- block reductions (fixed order) ------------------------------
__device__ __forceinline__ float blockReduceSum(float v, float* red) {
    #pragma unroll
    for (int o = 16; o; o >>= 1) v += __shfl_xor_sync(0xffffffffu, v, o);
    if ((threadIdx.x & 31) == 0) red[threadIdx.x >> 5] = v;
    __syncthreads();
    float t = 0.f;
    int nw = blockDim.x >> 5;
    for (int i = 0; i < nw; i++) t += red[i];
    __syncthreads();
    return t;
}
__device__ __forceinline__ float blockReduceMax(float v, float* red) {
    #pragma unroll
    for (int o = 16; o; o >>= 1) v = fmaxf(v, __shfl_xor_sync(0xffffffffu, v, o));
    if ((threadIdx.x & 31) == 0) red[threadIdx.x >> 5] = v;
    __syncthreads();
    float t = red[0];
    int nw = blockDim.x >> 5;
    for (int i = 1; i < nw; i++) t = fmaxf(t, red[i]);
    __syncthreads();
    return t;
}

// ---------------- one-time prep kernels ---------------------------------------
__global__ void k_transpose_bf16(const float* __restrict__ in, __nv_bfloat16* __restrict__ out, int R, int Ccols) {
    __shared__ float t[32][33];
    int c0 = blockIdx.x * 32, r0 = blockIdx.y * 32;
    #pragma unroll
    for (int i = 0; i < 4; i++)
        t[threadIdx.y + i * 8][threadIdx.x] = in[(size_t)(r0 + threadIdx.y + i * 8) * Ccols + c0 + threadIdx.x];
    __syncthreads();
    #pragma unroll
    for (int i = 0; i < 4; i++)
        out[(size_t)(c0 + threadIdx.y + i * 8) * R + r0 + threadIdx.x] =
            __float2bfloat16_rn(t[threadIdx.x][threadIdx.y + i * 8]);
}

// all plain fp32->bf16 conversions + zero-init in one launch (float4 index)
#define CVT_N0 ((size_t)Sdim * Bn * Cdim / 4)
#define CVT_N1 (CVT_N0 + (size_t)3 * Hdim * (Edim + Cdim) / 4)
#define CVT_N2 (CVT_N1 + (size_t)3 * Hdim * Hdim / 4)
#define CVT_N3 (CVT_N2 + (size_t)Edim * Hdim / 4)
#define CVT_N4 (CVT_N3 + (size_t)Edim * Cdim / 4)
#define CVT_N5 (CVT_N4 + (size_t)Vdim * Edim / 4)
#define CVT_N6 (CVT_N5 + (size_t)(Bn * Hdim) / 4)        // zero g_h
#define CVT_N7 (CVT_N6 + (size_t)(4 * Bn * Cdim) / 4)    // zero g_hq_part
__global__ void k_cvt_all(const float* __restrict__ ctx, const float* __restrict__ Wih,
                          const float* __restrict__ Whh, const float* __restrict__ h2o,
                          const float* __restrict__ octx, const float* __restrict__ o2p) {
    size_t i = (size_t)blockIdx.x * 256 + threadIdx.x;   // float4 index
    if (i >= CVT_N7) return;
    if (i >= CVT_N5) {
        float4 zz = make_float4(0.f, 0.f, 0.f, 0.f);
        if (i < CVT_N6) *(float4*)&g_h[(i - CVT_N5) * 4] = zz;
        else            *(float4*)&g_hq_part[(i - CVT_N6) * 4] = zz;
        return;
    }
    const float* src; __nv_bfloat16* dst; size_t off;
    if      (i < CVT_N0) { src = ctx;  dst = g_ctx_bf16;  off = i; }
    else if (i < CVT_N1) { src = Wih;  dst = g_Wih_bf16;  off = i - CVT_N0; }
    else if (i < CVT_N2) { src = Whh;  dst = g_Whh_bf16;  off = i - CVT_N1; }
    else if (i < CVT_N3) { src = h2o;  dst = g_h2o_bf16;  off = i - CVT_N2; }
    else if (i < CVT_N4) { src = octx; dst = g_octx_bf16; off = i - CVT_N3; }
    else                 { src = o2p;  dst = g_Wo2p_bf16; off = i - CVT_N4; }
    float4 v = *(const float4*)&src[off * 4];
    __nv_bfloat162* o = (__nv_bfloat162*)&dst[off * 4];
    o[0] = __floats2bfloat162_rn(v.x, v.y);
    o[1] = __floats2bfloat162_rn(v.z, v.w);
}

// ============ BF16 NT GEMM, 128x128, cp.async double-buffered (ctx_proj) ======
// dynamic smem: 2 buffers x (As 18432 + Bs 18432) = 73728 bytes
#define M128_BUF 36864
__global__ __launch_bounds__(256) void gemm_bf16_m128(
    const __nv_bfloat16* __restrict__ A, const __nv_bfloat16* __restrict__ B,
    __nv_bfloat16* __restrict__ C, int N, int K) {
    extern __shared__ __align__(16) unsigned char dynbuf[];
    const unsigned sbase = smem_u32(dynbuf);
    const int row0 = blockIdx.y * 128, col0 = blockIdx.x * 128;
    const int tid = threadIdx.x;
    const int wid = tid >> 5, lane = tid & 31;
    const int gID = lane >> 2, tig = lane & 3;
    const int m0w = (wid >> 2) * 64, n0w = (wid & 3) * 32;
    const int lrow = tid >> 1, lcol = (tid & 1) * 32;
    const int lmr = ((lane >> 3) & 1) * 8 + (lane & 7);
    const int lmcA = ((lane >> 4) & 1) * 8;
    const int lmrB = ((lane >> 4) & 1) * 8 + (lane & 7);
    const int lmcB = ((lane >> 3) & 1) * 8;
    float acc[4][4][4] = {};
    // issue tile 0 into buffer 0
    #pragma unroll
    for (int i = 0; i < 4; i++) {
        cpa16(sbase + (unsigned)((lrow * 72 + lcol + i * 8) * 2),
              &A[(size_t)(row0 + lrow) * K + lcol + i * 8]);
        cpa16(sbase + 18432u + (unsigned)((lrow * 72 + lcol + i * 8) * 2),
              &B[(size_t)(col0 + lrow) * K + lcol + i * 8]);
    }
    cpa_commit();
    int cur = 0;
    for (int k0 = 0; k0 < K; k0 += 64) {
        const bool has_next = (k0 + 64 < K);
        if (has_next) {
            const unsigned nb = (unsigned)(cur ^ 1) * M128_BUF;
            #pragma unroll
            for (int i = 0; i < 4; i++) {
                cpa16(sbase + nb + (unsigned)((lrow * 72 + lcol + i * 8) * 2),
                      &A[(size_t)(row0 + lrow) * K + k0 + 64 + lcol + i * 8]);
                cpa16(sbase + nb + 18432u + (unsigned)((lrow * 72 + lcol + i * 8) * 2),
                      &B[(size_t)(col0 + lrow) * K + k0 + 64 + lcol + i * 8]);
            }
            cpa_commit();
            cpa_wait1();
        } else {
            cpa_wait0();
        }
        __syncthreads();
        const unsigned cb = (unsigned)cur * M128_BUF;
        #pragma unroll
        for (int kk = 0; kk < 4; kk++) {
            const int kb = kk * 16;
            unsigned af[4][4], bf[4][2];
            #pragma unroll
            for (int mi = 0; mi < 4; mi++)
                ldmatrix_x4(af[mi], sbase + cb + (unsigned)(((m0w + mi * 16 + lmr) * 72 + kb + lmcA) * 2));
            #pragma unroll
            for (int nj = 0; nj < 2; nj++) {
                unsigned tmp[4];
                ldmatrix_x4(tmp, sbase + cb + 18432u + (unsigned)(((n0w + nj * 16 + lmrB) * 72 + kb + lmcB) * 2));
                bf[nj * 2][0] = tmp[0]; bf[nj * 2][1] = tmp[1];
                bf[nj * 2 + 1][0] = tmp[2]; bf[nj * 2 + 1][1] = tmp[3];
            }
            #pragma unroll
            for (int mi = 0; mi < 4; mi++)
                #pragma unroll
                for (int ni = 0; ni < 4; ni++)
                    mma_bf16(acc[mi][ni], af[mi], bf[ni]);
        }
        __syncthreads();
        cur ^= 1;
    }
    #pragma unroll
    for (int mi = 0; mi < 4; mi++)
        #pragma unroll
        for (int ni = 0; ni < 4; ni++) {
            int r = row0 + m0w + mi * 16 + gID;
            int c = col0 + n0w + ni * 8 + tig * 2;
            *(__nv_bfloat162*)&C[(size_t)r * N + c]       = __floats2bfloat162_rn(acc[mi][ni][0], acc[mi][ni][1]);
            *(__nv_bfloat162*)&C[(size_t)(r + 8) * N + c] = __floats2bfloat162_rn(acc[mi][ni][2], acc[mi][ni][3]);
        }
}

// ============ BF16 triple GEMM (o1, o2, hq-next), M=64, split-K, ldmatrix =====
__global__ __launch_bounds__(256) void gemm_bf16_m64_tri(
    const float* __restrict__ h, const float* __restrict__ z,
    const __nv_bfloat16* __restrict__ Bh2o, const __nv_bfloat16* __restrict__ Boctx,
    const __nv_bfloat16* __restrict__ Bhid,
    float* __restrict__ Co1, float* __restrict__ Co2, float* __restrict__ Chq) {
    const int prob = blockIdx.y;
    const float* A; const __nv_bfloat16* B; float* C; int N;
    if (prob == 0)      { A = h; B = Bh2o;  C = Co1; N = Edim; }
    else if (prob == 1) { A = z; B = Boctx; C = Co2; N = Edim; }
    else                { A = h; B = Bhid;  C = Chq; N = Cdim; }
    const int col0 = blockIdx.x * 64;
    if (col0 >= N) return;
    const int K = Hdim, kChunk = Hdim / 4;
    __shared__ __nv_bfloat16 As[64][72];
    __shared__ __nv_bfloat16 Bs[64][72];
    const int kbase = blockIdx.z * kChunk;
    const int tid = threadIdx.x;
    const int wid = tid >> 5, lane = tid & 31;
    const int gID = lane >> 2, tig = lane & 3;
    const int lrow = tid >> 2, lseg = (tid & 3) * 16;
    const int lmr = ((lane >> 3) & 1) * 8 + (lane & 7);
    const int lmcA = ((lane >> 4) & 1) * 8;
    const int lmrB2 = lane & 7;
    const int lmcB2 = ((lane >> 3) & 1) * 8;
    float acc[4][4] = {};
    for (int kt = 0; kt < kChunk; kt += 64) {
        const int k0 = kbase + kt;
        #pragma unroll
        for (int i = 0; i < 4; i++) {
            float4 a = *(const float4*)&A[(size_t)lrow * K + k0 + lseg + i * 4];
            __nv_bfloat162* d = (__nv_bfloat162*)&As[lrow][lseg + i * 4];
            d[0] = __floats2bfloat162_rn(a.x, a.y);
            d[1] = __floats2bfloat162_rn(a.z, a.w);
        }
        *(uint4*)&Bs[lrow][lseg]     = *(const uint4*)&B[(size_t)(col0 + lrow) * K + k0 + lseg];
        *(uint4*)&Bs[lrow][lseg + 8] = *(const uint4*)&B[(size_t)(col0 + lrow) * K + k0 + lseg + 8];
        __syncthreads();
        #pragma unroll
        for (int kk = 0; kk < 4; kk++) {
            const int kb = kk * 16;
            unsigned bfv[2];
            ldmatrix_x2(bfv, smem_u32(&Bs[wid * 8 + lmrB2][kb + lmcB2]));
            #pragma unroll
            for (int mi = 0; mi < 4; mi++) {
                unsigned af[4];
                ldmatrix_x4(af, smem_u32(&As[mi * 16 + lmr][kb + lmcA]));
                mma_bf16(acc[mi], af, bfv);
            }
        }
        __syncthreads();
    }
    float* Cp = C + (size_t)blockIdx.z * 64 * N;
    #pragma unroll
    for (int mi = 0; mi < 4; mi++) {
        int r = mi * 16 + gID;
        int c = col0 + wid * 8 + tig * 2;
        *(float2*)&Cp[(size_t)r * N + c]       = make_float2(acc[mi][0], acc[mi][1]);
        *(float2*)&Cp[(size_t)(r + 8) * N + c] = make_float2(acc[mi][2], acc[mi][3]);
    }
}

// ============ merged GRU GEMMs (bf16, ldmatrix): y=0 -> gi, y=1 -> gh =========
__global__ __launch_bounds__(256) void gemm_bf16_gigh_sk(
    const float* __restrict__ embW, const int* __restrict__ y, int t,
    const __nv_bfloat16* __restrict__ Wih, float* __restrict__ Cgi,
    const __nv_bfloat16* __restrict__ Whh, float* __restrict__ Cgh) {
    const bool is_gi = (blockIdx.y == 0);
    const int K      = is_gi ? (Edim + Cdim) : Hdim;
    const int kChunk = is_gi ? ((Edim + Cdim) / 4) : (Hdim / 4);
    const __nv_bfloat16* B = is_gi ? Wih : Whh;
    float* C = is_gi ? Cgi : Cgh;
    const int N = 3 * Hdim;
    __shared__ __nv_bfloat16 As[64][72];
    __shared__ __nv_bfloat16 Bs[64][72];
    const int col0 = blockIdx.x * 64;
    const int kbase = blockIdx.z * kChunk;
    const int tid = threadIdx.x;
    const int wid = tid >> 5, lane = tid & 31;
    const int gID = lane >> 2, tig = lane & 3;
    const int lrow = tid >> 2, lseg = (tid & 3) * 16;
    const int lmr = ((lane >> 3) & 1) * 8 + (lane & 7);
    const int lmcA = ((lane >> 4) & 1) * 8;
    const int lmrB2 = lane & 7;
    const int lmcB2 = ((lane >> 3) & 1) * 8;
    const int yid = is_gi ? y[t * Bn + lrow] : 0;
    float acc[4][4] = {};
    for (int kt = 0; kt < kChunk; kt += 64) {
        const int k0 = kbase + kt;
        const float* Arow;
        if (is_gi) Arow = (k0 < Edim) ? &embW[(size_t)yid * Edim + k0]
                                      : &g_z[lrow * Cdim + (k0 - Edim)];
        else       Arow = &g_h[lrow * Hdim + k0];
        #pragma unroll
        for (int i = 0; i < 4; i++) {
            float4 a = *(const float4*)&Arow[lseg + i * 4];
            __nv_bfloat162* d = (__nv_bfloat162*)&As[lrow][lseg + i * 4];
            d[0] = __floats2bfloat162_rn(a.x, a.y);
            d[1] = __floats2bfloat162_rn(a.z, a.w);
        }
        *(uint4*)&Bs[lrow][lseg]     = *(const uint4*)&B[(size_t)(col0 + lrow) * K + k0 + lseg];
        *(uint4*)&Bs[lrow][lseg + 8] = *(const uint4*)&B[(size_t)(col0 + lrow) * K + k0 + lseg + 8];
        __syncthreads();
        #pragma unroll
        for (int kk = 0; kk < 4; kk++) {
            const int kb = kk * 16;
            unsigned bfv[2];
            ldmatrix_x2(bfv, smem_u32(&Bs[wid * 8 + lmrB2][kb + lmcB2]));
            #pragma unroll
            for (int mi = 0; mi < 4; mi++) {
                unsigned af[4];
                ldmatrix_x4(af, smem_u32(&As[mi * 16 + lmr][kb + lmcA]));
                mma_bf16(acc[mi], af, bfv);
            }
        }
        __syncthreads();
    }
    float* Cp = C + (size_t)blockIdx.z * 64 * N;
    #pragma unroll
    for (int mi = 0; mi < 4; mi++) {
        int r = mi * 16 + gID;
        int c = col0 + wid * 8 + tig * 2;
        *(float2*)&Cp[(size_t)r * N + c]       = make_float2(acc[mi][0], acc[mi][1]);
        *(float2*)&Cp[(size_t)(r + 8) * N + c] = make_float2(acc[mi][2], acc[mi][3]);
    }
}

// ============ BF16 logits GEMM + fused NLL, cp.async double-buffered ==========
// dynamic smem: 2 buffers x (As 9216 + Bs 36864) = 92160 bytes
#define LGT_BUF 46080
__global__ __launch_bounds__(256) void gemm_bf16_logits_nll(
    const __nv_bfloat16* __restrict__ A, const __nv_bfloat16* __restrict__ B,
    const float* __restrict__ bias, const int* __restrict__ y, int t, int K) {
    extern __shared__ __align__(16) unsigned char dynbuf[];
    const unsigned sbase = smem_u32(dynbuf);
    float (*sm)[8] = reinterpret_cast<float(*)[8]>(dynbuf);         // overlays buf0 As
    float (*ss)[8] = reinterpret_cast<float(*)[8]>(dynbuf + 2048);
    const int col0 = blockIdx.x * 256;
    const int tid = threadIdx.x;
    const int wid = tid >> 5, lane = tid & 31;
    const int gID = lane >> 2, tig = lane & 3;
    const int n0w = wid * 32;
    const int lmr = ((lane >> 3) & 1) * 8 + (lane & 7);
    const int lmcA = ((lane >> 4) & 1) * 8;
    const int lmrB = ((lane >> 4) & 1) * 8 + (lane & 7);
    const int lmcB = ((lane >> 3) & 1) * 8;
    const int ar = tid >> 2, as = (tid & 3) * 16;
    float acc[4][4][4] = {};
    // issue tile 0 -> buffer 0
    cpa16(sbase + (unsigned)((ar * 72 + as) * 2),     &A[(size_t)ar * K + as]);
    cpa16(sbase + (unsigned)((ar * 72 + as + 8) * 2), &A[(size_t)ar * K + as + 8]);
    #pragma unroll
    for (int i = 0; i < 8; i++)
        cpa16(sbase + 9216u + (unsigned)((tid * 72 + i * 8) * 2),
              &B[(size_t)(col0 + tid) * K + i * 8]);
    cpa_commit();
    int cur = 0;
    for (int k0 = 0; k0 < K; k0 += 64) {
        const bool has_next = (k0 + 64 < K);
        if (has_next) {
            const unsigned nb = (unsigned)(cur ^ 1) * LGT_BUF;
            cpa16(sbase + nb + (unsigned)((ar * 72 + as) * 2),     &A[(size_t)ar * K + k0 + 64 + as]);
            cpa16(sbase + nb + (unsigned)((ar * 72 + as + 8) * 2), &A[(size_t)ar * K + k0 + 64 + as + 8]);
            #pragma unroll
            for (int i = 0; i < 8; i++)
                cpa16(sbase + nb + 9216u + (unsigned)((tid * 72 + i * 8) * 2),
                      &B[(size_t)(col0 + tid) * K + k0 + 64 + i * 8]);
            cpa_commit();
            cpa_wait1();
        } else {
            cpa_wait0();
        }
        __syncthreads();
        const unsigned cb = (unsigned)cur * LGT_BUF;
        #pragma unroll
        for (int kk = 0; kk < 4; kk++) {
            const int kb = kk * 16;
            unsigned af[4][4], bf[4][2];
            #pragma unroll
            for (int mi = 0; mi < 4; mi++)
                ldmatrix_x4(af[mi], sbase + cb + (unsigned)(((mi * 16 + lmr) * 72 + kb + lmcA) * 2));
            #pragma unroll
            for (int nj = 0; nj < 2; nj++) {
                unsigned tmp[4];
                ldmatrix_x4(tmp, sbase + cb + 9216u + (unsigned)(((n0w + nj * 16 + lmrB) * 72 + kb + lmcB) * 2));
                bf[nj * 2][0] = tmp[0]; bf[nj * 2][1] = tmp[1];
                bf[nj * 2 + 1][0] = tmp[2]; bf[nj * 2 + 1][1] = tmp[3];
            }
            #pragma unroll
            for (int mi = 0; mi < 4; mi++)
                #pragma unroll
                for (int ni = 0; ni < 4; ni++)
                    mma_bf16(acc[mi][ni], af[mi], bf[ni]);
        }
        __syncthreads();
        cur ^= 1;
    }
    // epilogue: buf0 As region is dead (last mma finished, fenced by final sync)
    #pragma unroll
    for (int mi = 0; mi < 4; mi++) {
        const int r  = mi * 16 + gID;
        const int r2 = r + 8;
        const int tgt  = y[(t + 1) * Bn + r];
        const int tgt2 = y[(t + 1) * Bn + r2];
        float m1 = -1e30f, s1 = 0.f, m2 = -1e30f, s2 = 0.f;
        #pragma unroll
        for (int ni = 0; ni < 4; ni++) {
            int c = col0 + n0w + ni * 8 + tig * 2;
            float b0 = bias[c], b1 = bias[c + 1];
            float v0 = acc[mi][ni][0] + b0, v1 = acc[mi][ni][1] + b1;
            float v2 = acc[mi][ni][2] + b0, v3 = acc[mi][ni][3] + b1;
            if (c == tgt)      g_ltgt[r]  = v0;
            if (c + 1 == tgt)  g_ltgt[r]  = v1;
            if (c == tgt2)     g_ltgt[r2] = v2;
            if (c + 1 == tgt2) g_ltgt[r2] = v3;
            lse_upd(m1, s1, v0); lse_upd(m1, s1, v1);
            lse_upd(m2, s2, v2); lse_upd(m2, s2, v3);
        }
        #pragma unroll
        for (int off = 1; off <= 2; off <<= 1) {
            float om = __shfl_xor_sync(0xffffffffu, m1, off);
            float os = __shfl_xor_sync(0xffffffffu, s1, off);
            lse_comb(m1, s1, om, os);
            om = __shfl_xor_sync(0xffffffffu, m2, off);
            os = __shfl_xor_sync(0xffffffffu, s2, off);
            lse_comb(m2, s2, om, os);
        }
        if (tig == 0) {
            sm[r][wid] = m1; ss[r][wid] = s1;
            sm[r2][wid] = m2; ss[r2][wid] = s2;
        }
    }
    __syncthreads();
    if (tid < 64) {
        float M = sm[tid][0], S = ss[tid][0];
        #pragma unroll
        for (int w = 1; w < 8; w++) lse_comb(M, S, sm[tid][w], ss[tid][w]);
        g_pm[blockIdx.x * Bn + tid] = M;
        g_ps[blockIdx.x * Bn + tid] = S;
    }
}

// ============ fused attention + previous step's NLL finalize ==================
__global__ __launch_bounds__(256) void k_att(const float* __restrict__ mlp,
                                             const int* __restrict__ y, int t) {
    const int b = blockIdx.x;
    const int tid = threadIdx.x;
    const int wid = tid >> 5, lane = tid & 31;
    __shared__ float sc[200];
    __shared__ float red[8];
    if (t > 0 && wid == 7) {
        float m = -1e30f, s = 0.f;
        for (int i = lane; i < NVBLK; i += 32)
            lse_comb(m, s, g_pm[i * Bn + b], g_ps[i * Bn + b]);
        #pragma unroll
        for (int off = 16; off; off >>= 1) {
            float om = __shfl_xor_sync(0xffffffffu, m, off);
            float os = __shfl_xor_sync(0xffffffffu, s, off);
            lse_comb(m, s, om, os);
        }
        if (lane == 0) {
            int tgt = y[t * Bn + b];
            g_nll[(t - 1) * Bn + b] = (tgt != 0) ? (m + logf(s) - g_ltgt[b]) : 0.f;
        }
    }
    float hqv[32], mlpv[32];
    #pragma unroll
    for (int j = 0; j < 4; j++) {
        #pragma unroll
        for (int u = 0; u < 8; u++) {
            int m = lane * 8 + j * 256 + u;
            float v = g_hq_part[b * Cdim + m]
                    + g_hq_part[(Bn + b) * Cdim + m]
                    + g_hq_part[(2 * Bn + b) * Cdim + m]
                    + g_hq_part[(3 * Bn + b) * Cdim + m];
            hqv[j * 8 + u] = v;
            mlpv[j * 8 + u] = mlp[m];
        }
    }
    for (int s = wid; s < Sdim; s += 8) {
        const __nv_bfloat16* row = g_ctxp_bf16 + ((size_t)s * Bn + b) * Cdim;
        float sum = 0.f;
        #pragma unroll
        for (int j = 0; j < 4; j++) {
            int m = lane * 8 + j * 256;
            uint4 u = *(const uint4*)&row[m];
            float2 f0 = __bfloat1622float2(*(__nv_bfloat162*)&u.x);
            float2 f1 = __bfloat1622float2(*(__nv_bfloat162*)&u.y);
            float2 f2 = __bfloat1622float2(*(__nv_bfloat162*)&u.z);
            float2 f3 = __bfloat1622float2(*(__nv_bfloat162*)&u.w);
            sum += ftanh_fast(f0.x + hqv[j * 8 + 0]) * mlpv[j * 8 + 0];
            sum += ftanh_fast(f0.y + hqv[j * 8 + 1]) * mlpv[j * 8 + 1];
            sum += ftanh_fast(f1.x + hqv[j * 8 + 2]) * mlpv[j * 8 + 2];
            sum += ftanh_fast(f1.y + hqv[j * 8 + 3]) * mlpv[j * 8 + 3];
            sum += ftanh_fast(f2.x + hqv[j * 8 + 4]) * mlpv[j * 8 + 4];
            sum += ftanh_fast(f2.y + hqv[j * 8 + 5]) * mlpv[j * 8 + 5];
            sum += ftanh_fast(f3.x + hqv[j * 8 + 6]) * mlpv[j * 8 + 6];
            sum += ftanh_fast(f3.y + hqv[j * 8 + 7]) * mlpv[j * 8 + 7];
        }
        #pragma unroll
        for (int o = 16; o; o >>= 1) sum += __shfl_xor_sync(0xffffffffu, sum, o);
        if (lane == 0) sc[s] = sum;
    }
    __syncthreads();
    float v = (tid < Sdim) ? sc[tid] : -1e30f;
    float mx = blockReduceMax(v, red);
    float e = (tid < Sdim) ? __expf(v - mx) : 0.f;
    float tot = blockReduceSum(e, red);
    if (tid < Sdim) sc[tid] = __fdividef(e, tot);
    __syncthreads();
    const int c4 = tid * 4;
    float4 acc = make_float4(0.f, 0.f, 0.f, 0.f);
    #pragma unroll 4
    for (int s = 0; s < Sdim; s++) {
        float a = sc[s];
        uint2 u = *(const uint2*)&g_ctx_bf16[((size_t)s * Bn + b) * Cdim + c4];
        float2 f0 = __bfloat1622float2(*(__nv_bfloat162*)&u.x);
        float2 f1 = __bfloat1622float2(*(__nv_bfloat162*)&u.y);
        acc.x = fmaf(a, f0.x, acc.x); acc.y = fmaf(a, f0.y, acc.y);
        acc.z = fmaf(a, f1.x, acc.z); acc.w = fmaf(a, f1.y, acc.w);
    }
    *(float4*)&g_z[b * Cdim + c4] = acc;
}

// ---------------- per-step elementwise kernels --------------------------------
__global__ void k_gru(const float* __restrict__ b_ih, const float* __restrict__ b_hh) {
    const int i = blockIdx.x * 256 + threadIdx.x;
    const int b = i >> 10, j = i & (Hdim - 1);
    float ir = b_ih[j], iz = b_ih[Hdim + j], in_ = b_ih[2 * Hdim + j];
    #pragma unroll
    for (int p = 0; p < 4; p++) {
        const float* g = g_gi_part + ((size_t)p * Bn + b) * 3 * Hdim;
        ir += g[j]; iz += g[Hdim + j]; in_ += g[2 * Hdim + j];
    }
    float hr = b_hh[j], hz = b_hh[Hdim + j], hn = b_hh[2 * Hdim + j];
    #pragma unroll
    for (int p = 0; p < 4; p++) {
        const float* g = g_gh_part + ((size_t)p * Bn + b) * 3 * Hdim;
        hr += g[j]; hz += g[Hdim + j]; hn += g[2 * Hdim + j];
    }
    float r = fsig(ir + hr);
    float zz = fsig(iz + hz);
    float n = ftanh(in_ + r * hn);
    float hold = g_h[i];
    g_h[i] = (1.f - zz) * n + zz * hold;
}

__global__ void k_pvec(const float* __restrict__ embW, const int* __restrict__ y,
                       const float* __restrict__ h2o_b, const float* __restrict__ octx_b, int t) {
    const int i = blockIdx.x * 256 + threadIdx.x;
    const int b = i >> 9, e = i & (Edim - 1);
    float o1 = h2o_b[e], o2 = octx_b[e];
    #pragma unroll
    for (int p = 0; p < 4; p++) {
        o1 += g_o1_part[p * Bn * Edim + i];
        o2 += g_o2_part[p * Bn * Edim + i];
    }
    float l = ftanh(o1);
    l += embW[(size_t)y[t * Bn + b] * Edim + e];
    l += o2;
    g_p_bf16[i] = __float2bfloat16_rn(ftanh(l));
}

// final: last step's NLL from partials + total sum
__global__ __launch_bounds__(256) void k_final(const int* __restrict__ y, float* __restrict__ out) {
    __shared__ float red[8];
    const int tid = threadIdx.x;
    if (tid < Bn) {
        float m = -1e30f, s = 0.f;
        for (int i = 0; i < NVBLK; i++)
            lse_comb(m, s, g_pm[i * Bn + tid], g_ps[i * Bn + tid]);
        int tgt = y[NSTEP * Bn + tid];
        g_nll[(NSTEP - 1) * Bn + tid] = (tgt != 0) ? (m + logf(s) - g_ltgt[tid]) : 0.f;
    }
    __syncthreads();
    float s = 0.f;
    for (int i = tid; i < NSTEP * Bn; i += 256) s += g_nll[i];
    float tot = blockReduceSum(s, red);
    if (tid == 0) out[0] = tot;
}

// ---------------- launch ------------------------------------------------------
extern "C" void kernel_launch(void* const* d_in, const int* in_sizes, int n_in,
                              void* d_out, int out_size) {
    const float* ctx         = (const float*)d_in[0];
    const int*   y           = (const int*)  d_in[1];
    const float* embW        = (const float*)d_in[2];
    const float* att_ctx2ctx = (const float*)d_in[3];
    const float* att_hid2ctx = (const float*)d_in[4];
    const float* att_mlp     = (const float*)d_in[5];
    const float* gru_W_ih    = (const float*)d_in[6];
    const float* gru_b_ih    = (const float*)d_in[7];
    const float* gru_W_hh    = (const float*)d_in[8];
    const float* gru_b_hh    = (const float*)d_in[9];
    const float* h2o_W       = (const float*)d_in[10];
    const float* h2o_b       = (const float*)d_in[11];
    const float* octx_W      = (const float*)d_in[12];
    const float* octx_b      = (const float*)d_in[13];
    const float* o2p_W       = (const float*)d_in[14];
    const float* o2p_b       = (const float*)d_in[15];

    float *p_h, *p_hqp, *p_z, *p_gip, *p_ghp, *p_o1p, *p_o2p;
    __nv_bfloat16 *p_ctxpbf, *p_ctxbf, *p_WctxTbf, *p_WhidTbf, *p_Wihbf, *p_Whhbf,
                  *p_h2obf, *p_octxbf, *p_Wbf, *p_pbf;
    cudaGetSymbolAddress((void**)&p_ctxpbf,  g_ctxp_bf16);
    cudaGetSymbolAddress((void**)&p_ctxbf,   g_ctx_bf16);
    cudaGetSymbolAddress((void**)&p_WctxTbf, g_WctxT_bf16);
    cudaGetSymbolAddress((void**)&p_WhidTbf, g_WhidT_bf16);
    cudaGetSymbolAddress((void**)&p_Wihbf,   g_Wih_bf16);
    cudaGetSymbolAddress((void**)&p_Whhbf,   g_Whh_bf16);
    cudaGetSymbolAddress((void**)&p_h2obf,   g_h2o_bf16);
    cudaGetSymbolAddress((void**)&p_octxbf,  g_octx_bf16);
    cudaGetSymbolAddress((void**)&p_Wbf,     g_Wo2p_bf16);
    cudaGetSymbolAddress((void**)&p_pbf,     g_p_bf16);
    cudaGetSymbolAddress((void**)&p_h,       g_h);
    cudaGetSymbolAddress((void**)&p_hqp,     g_hq_part);
    cudaGetSymbolAddress((void**)&p_z,       g_z);
    cudaGetSymbolAddress((void**)&p_gip,     g_gi_part);
    cudaGetSymbolAddress((void**)&p_ghp,     g_gh_part);
    cudaGetSymbolAddress((void**)&p_o1p,     g_o1_part);
    cudaGetSymbolAddress((void**)&p_o2p,     g_o2_part);

    cudaFuncSetAttribute(gemm_bf16_m128,
                         cudaFuncAttributeMaxDynamicSharedMemorySize, 2 * M128_BUF);
    cudaFuncSetAttribute(gemm_bf16_logits_nll,
                         cudaFuncAttributeMaxDynamicSharedMemorySize, 2 * LGT_BUF);

    // one-time prep (zero-init folded into k_cvt_all)
    k_cvt_all<<<(unsigned)((CVT_N7 + 255) / 256), 256>>>(ctx, gru_W_ih, gru_W_hh,
                                                         h2o_W, octx_W, o2p_W);
    k_transpose_bf16<<<dim3(32, 32), dim3(32, 8)>>>(att_ctx2ctx, p_WctxTbf, Cdim, Cdim);
    k_transpose_bf16<<<dim3(32, 32), dim3(32, 8)>>>(att_hid2ctx, p_WhidTbf, Hdim, Cdim);
    gemm_bf16_m128<<<dim3(Cdim / 128, (Sdim * Bn) / 128), 256, 2 * M128_BUF>>>(
        p_ctxbf, p_WctxTbf, p_ctxpbf, Cdim, Cdim);

    for (int t = 0; t < NSTEP; t++) {
        k_att<<<Bn, 256>>>(att_mlp, y, t);
        gemm_bf16_gigh_sk<<<dim3((3 * Hdim) / 64, 2, 4), 256>>>(
            embW, y, t, p_Wihbf, p_gip, p_Whhbf, p_ghp);
        k_gru<<<(Bn * Hdim) / 256, 256>>>(gru_b_ih, gru_b_hh);
        gemm_bf16_m64_tri<<<dim3(Cdim / 64, 3, 4), 256>>>(
            p_h, p_z, p_h2obf, p_octxbf, p_WhidTbf, p_o1p, p_o2p, p_hqp);
        k_pvec<<<(Bn * Edim) / 256, 256>>>(embW, y, h2o_b, octx_b, t);
        gemm_bf16_logits_nll<<<NVBLK, 256, 2 * LGT_BUF>>>(p_pbf, p_Wbf, o2p_b, y, t, Edim);
    }
    k_final<<<1, 256>>>(y, (float*)d_out);
}